// round 7
// baseline (speedup 1.0000x reference)
#include <cuda_runtime.h>
#include <cstdint>

#define N_  512
#define C_  128
#define NN_ (N_*N_)
#define KK_ 64                 // k-pairs per 128-length row
#define XLD 66                 // padded uint2 row for proj smem
#define TLD 18                 // padded uint2 row for tri smem (16 kk chunk)
#define SSTG (128*TLD)         // uint2 per tri stage per matrix

// scratch device globals (packed uint2 = (bf16x2 hi, bf16x2 lo) per k-pair)
__device__ uint2 g_znp[(size_t)NN_*KK_];        // LN(z) packed; reused for LN(o)
__device__ uint2 g_atp[(size_t)C_*(NN_/2)];     // a packed, c-major [c][r/2]
__device__ uint2 g_btp[(size_t)C_*(NN_/2)];     // b packed, c-major
__device__ float g_gt [(size_t)NN_*C_];         // gate fp32 row-major
__device__ float g_ot [(size_t)NN_*C_];         // einsum out, c-major
__device__ float g_o  [(size_t)NN_*C_];         // o row-major
__device__ uint2 g_wp [6*C_*KK_];               // packed weights [n][kk]

// ---------------------------------------------------------------------------
__device__ __forceinline__ float sigf(float x) { return 1.f / (1.f + __expf(-x)); }

// pack two fp32 into (hi bf16x2, lo bf16x2); low half of each reg = x0
__device__ __forceinline__ uint2 pack_split(float x0, float x1) {
    uint32_t h, l;
    asm("cvt.rn.bf16x2.f32 %0, %1, %2;" : "=r"(h) : "f"(x1), "f"(x0));
    float h0 = __uint_as_float(h << 16);
    float h1 = __uint_as_float(h & 0xffff0000u);
    float r0 = x0 - h0, r1 = x1 - h1;
    asm("cvt.rn.bf16x2.f32 %0, %1, %2;" : "=r"(l) : "f"(r1), "f"(r0));
    return make_uint2(h, l);
}

__device__ __forceinline__ void mma_bf16(float* c, const uint32_t* a, const uint32_t* b) {
    asm volatile(
        "mma.sync.aligned.m16n8k16.row.col.f32.bf16.bf16.f32 "
        "{%0,%1,%2,%3},{%4,%5,%6,%7},{%8,%9},{%0,%1,%2,%3};\n"
        : "+f"(c[0]), "+f"(c[1]), "+f"(c[2]), "+f"(c[3])
        : "r"(a[0]), "r"(a[1]), "r"(a[2]), "r"(a[3]), "r"(b[0]), "r"(b[1]));
}

__device__ __forceinline__ void cp16(void* dst, const void* src) {
    unsigned s = (unsigned)__cvta_generic_to_shared(dst);
    asm volatile("cp.async.cg.shared.global [%0], [%1], 16;\n" :: "r"(s), "l"(src));
}
__device__ __forceinline__ void cp_commit() { asm volatile("cp.async.commit_group;\n"); }

// A-frag (both planes) for one 16-row group: rows r,r+8; kk, kk+4
#define LDA(ap, ldk, r, kk, AH, AL) do {                 \
    uint2 v0 = (ap)[(r)*(ldk) + (kk)];                   \
    uint2 v1 = (ap)[((r)+8)*(ldk) + (kk)];               \
    uint2 v2 = (ap)[(r)*(ldk) + (kk) + 4];               \
    uint2 v3 = (ap)[((r)+8)*(ldk) + (kk) + 4];           \
    AH[0]=v0.x; AL[0]=v0.y; AH[1]=v1.x; AL[1]=v1.y;      \
    AH[2]=v2.x; AL[2]=v2.y; AH[3]=v3.x; AL[3]=v3.y;      \
} while(0)

#define LDB(bp, ldk, n, kk, BH, BL) do {                 \
    uint2 u0 = (bp)[(n)*(ldk) + (kk)];                   \
    uint2 u1 = (bp)[(n)*(ldk) + (kk) + 4];               \
    BH[0]=u0.x; BL[0]=u0.y; BH[1]=u1.x; BL[1]=u1.y;      \
} while(0)

// ---------------------------------------------------------------------------
// one-time weight split: W[128x128] fp32 -> packed uint2 [n][kk]
// ---------------------------------------------------------------------------
__global__ __launch_bounds__(256) void split_w_kernel(
    const float* __restrict__ w0, const float* __restrict__ w1,
    const float* __restrict__ w2, const float* __restrict__ w3,
    const float* __restrict__ w4, const float* __restrict__ w5,
    uint2* __restrict__ wp)
{
    int which = blockIdx.y;
    const float* w = which==0?w0 : which==1?w1 : which==2?w2 :
                     which==3?w3 : which==4?w4 : w5;
    int idx = blockIdx.x*256 + threadIdx.x;      // 0..8191 pairs
    int n = idx >> 6, kk = idx & 63;
    wp[which*C_*KK_ + idx] = pack_split(w[n*C_ + kk*2], w[n*C_ + kk*2 + 1]);
}

// ---------------------------------------------------------------------------
// LayerNorm over C=128, output packed bf16 hi/lo
// ---------------------------------------------------------------------------
__global__ __launch_bounds__(128) void ln_pack_kernel(
    const float* __restrict__ x, const float* __restrict__ w,
    const float* __restrict__ b, uint2* __restrict__ yp)
{
    size_t row = blockIdx.x;
    int c = threadIdx.x;
    float v = x[row*C_ + c];
    float s = v, s2 = v*v;
    #pragma unroll
    for (int o = 16; o; o >>= 1) {
        s  += __shfl_xor_sync(0xffffffffu, s, o);
        s2 += __shfl_xor_sync(0xffffffffu, s2, o);
    }
    __shared__ float sh[8];
    int wid = c >> 5;
    if ((c & 31) == 0) { sh[wid] = s; sh[wid + 4] = s2; }
    __syncthreads();
    s  = sh[0] + sh[1] + sh[2] + sh[3];
    s2 = sh[4] + sh[5] + sh[6] + sh[7];
    float mu  = s  * (1.0f / C_);
    float var = s2 * (1.0f / C_) - mu * mu;
    float inv = rsqrtf(var + 1e-5f);
    float yv = (v - mu) * inv * w[c] + b[c];
    float yn = __shfl_down_sync(0xffffffffu, yv, 1);
    if ((c & 1) == 0)
        yp[row*KK_ + (c >> 1)] = pack_split(yv, yn);
}

// ---------------------------------------------------------------------------
// transpose: out[c][r] = in[r][c]
// ---------------------------------------------------------------------------
__global__ __launch_bounds__(256) void transpose_kernel(
    const float* __restrict__ in, float* __restrict__ out, int R, int C)
{
    __shared__ float tile[32][33];
    size_t c0 = (size_t)blockIdx.x * 32, r0 = (size_t)blockIdx.y * 32;
    int tx = threadIdx.x, ty = threadIdx.y;
    #pragma unroll
    for (int k = 0; k < 4; k++)
        tile[ty + k*8][tx] = in[(r0 + ty + k*8) * C + c0 + tx];
    __syncthreads();
    #pragma unroll
    for (int k = 0; k < 4; k++)
        out[(c0 + ty + k*8) * R + r0 + tx] = tile[tx][ty + k*8];
}

// ---------------------------------------------------------------------------
// proj_dual: Yc packed c-major = split( mask[r] * sigmoid(X@W1^T) * (X@W2^T) )
// 512 thr, 16 warps (4M x 4N), warp tile 32x32 per GEMM, K=128 resident.
// Term-major MMA ordering: all HH, then LH, then HL -> no same-acc chains.
// ---------------------------------------------------------------------------
__global__ __launch_bounds__(512, 1) void proj_dual(
    const uint2* __restrict__ Xp, const uint2* __restrict__ W1p,
    const uint2* __restrict__ W2p, const float* __restrict__ mask,
    uint2* __restrict__ Yp)
{
    extern __shared__ uint2 smu[];
    uint2* xs  = smu;                // [128][XLD]
    uint2* w1s = smu + 128*XLD;
    uint2* w2s = smu + 2*128*XLD;

    int t = threadIdx.x, warp = t>>5, lane = t&31, g = lane>>2, tg = lane&3;
    size_t row0 = (size_t)blockIdx.x * 128;
    int m0 = (warp & 3) * 32;
    int n0 = (warp >> 2) * 32;

    #pragma unroll
    for (int i = 0; i < 8; i++) {
        int e = i*512 + t;           // 0..4095, 16B chunks
        int r = e >> 5, q = (e & 31) * 2;
        cp16(xs  + r*XLD + q, Xp  + (row0 + r)*KK_ + q);
        cp16(w1s + r*XLD + q, W1p + r*KK_ + q);
        cp16(w2s + r*XLD + q, W2p + r*KK_ + q);
    }
    cp_commit();
    asm volatile("cp.async.wait_group 0;\n");
    __syncthreads();

    float acc1[2][4][4], acc2[2][4][4];
    #pragma unroll
    for (int mt=0; mt<2; mt++)
        #pragma unroll
        for (int nt=0; nt<4; nt++)
            #pragma unroll
            for (int q=0; q<4; q++) { acc1[mt][nt][q]=0.f; acc2[mt][nt][q]=0.f; }

    #pragma unroll
    for (int ks = 0; ks < 8; ks++) {
        int kb = ks*8 + tg;
        // preload ALL fragments for this k-chunk
        uint32_t Ah[2][4], Al[2][4];
        #pragma unroll
        for (int mt=0; mt<2; mt++)
            LDA(xs, XLD, m0 + mt*16 + g, kb, Ah[mt], Al[mt]);
        uint32_t B1h[4][2], B1l[4][2], B2h[4][2], B2l[4][2];
        #pragma unroll
        for (int nt=0; nt<4; nt++) {
            LDB(w1s, XLD, n0 + nt*8 + g, kb, B1h[nt], B1l[nt]);
            LDB(w2s, XLD, n0 + nt*8 + g, kb, B2h[nt], B2l[nt]);
        }
        // HH term: 16 independent MMAs
        #pragma unroll
        for (int nt=0; nt<4; nt++)
            #pragma unroll
            for (int mt=0; mt<2; mt++) {
                mma_bf16(acc1[mt][nt], Ah[mt], B1h[nt]);
                mma_bf16(acc2[mt][nt], Ah[mt], B2h[nt]);
            }
        // LH term
        #pragma unroll
        for (int nt=0; nt<4; nt++)
            #pragma unroll
            for (int mt=0; mt<2; mt++) {
                mma_bf16(acc1[mt][nt], Al[mt], B1h[nt]);
                mma_bf16(acc2[mt][nt], Al[mt], B2h[nt]);
            }
        // HL term
        #pragma unroll
        for (int nt=0; nt<4; nt++)
            #pragma unroll
            for (int mt=0; mt<2; mt++) {
                mma_bf16(acc1[mt][nt], Ah[mt], B1l[nt]);
                mma_bf16(acc2[mt][nt], Ah[mt], B2l[nt]);
            }
    }

    // epilogue: fp32 tile in smem, then packed c-major store
    __syncthreads();
    float* so = (float*)smu;        // [128][132]
    #pragma unroll
    for (int mt=0; mt<2; mt++) {
        int rl = m0 + mt*16 + g, rh = rl + 8;
        float ml = mask[row0 + rl], mh = mask[row0 + rh];
        #pragma unroll
        for (int nt=0; nt<4; nt++) {
            int cl = n0 + nt*8 + 2*tg;
            so[rl*132 + cl]     = ml * sigf(acc1[mt][nt][0]) * acc2[mt][nt][0];
            so[rl*132 + cl + 1] = ml * sigf(acc1[mt][nt][1]) * acc2[mt][nt][1];
            so[rh*132 + cl]     = mh * sigf(acc1[mt][nt][2]) * acc2[mt][nt][2];
            so[rh*132 + cl + 1] = mh * sigf(acc1[mt][nt][3]) * acc2[mt][nt][3];
        }
    }
    __syncthreads();
    int c  = t >> 2;
    int p0 = (t & 3) * 16;
    size_t base = (size_t)c * (NN_/2) + row0/2;
    #pragma unroll
    for (int p = 0; p < 16; p++) {
        int pr = p0 + p;
        Yp[base + pr] = pack_split(so[(2*pr)*132 + c], so[(2*pr+1)*132 + c]);
    }
}

// ---------------------------------------------------------------------------
// proj_single: MODE 1: Y = sigmoid(X@W^T); MODE 2: Y = extra .* (X@W^T)
// 512 thr, 16 warps (4M x 4N), warp tile 32x32, K=128 resident.
// ---------------------------------------------------------------------------
template<int MODE>
__global__ __launch_bounds__(512, 1) void proj_single(
    const uint2* __restrict__ Xp, const uint2* __restrict__ Wp,
    const float* __restrict__ extra, float* __restrict__ Y)
{
    extern __shared__ uint2 smu[];
    uint2* xs = smu;                 // [128][XLD]
    uint2* ws = smu + 128*XLD;

    int t = threadIdx.x, warp = t>>5, lane = t&31, g = lane>>2, tg = lane&3;
    size_t row0 = (size_t)blockIdx.x * 128;
    int m0 = (warp & 3) * 32;
    int n0 = (warp >> 2) * 32;

    #pragma unroll
    for (int i = 0; i < 8; i++) {
        int e = i*512 + t;
        int r = e >> 5, q = (e & 31) * 2;
        cp16(xs + r*XLD + q, Xp + (row0 + r)*KK_ + q);
        cp16(ws + r*XLD + q, Wp + r*KK_ + q);
    }
    cp_commit();
    asm volatile("cp.async.wait_group 0;\n");
    __syncthreads();

    float acc[2][4][4];
    #pragma unroll
    for (int mt=0; mt<2; mt++)
        #pragma unroll
        for (int nt=0; nt<4; nt++)
            #pragma unroll
            for (int q=0; q<4; q++) acc[mt][nt][q]=0.f;

    #pragma unroll
    for (int ks = 0; ks < 8; ks++) {
        int kb = ks*8 + tg;
        uint32_t Ah[2][4], Al[2][4];
        #pragma unroll
        for (int mt=0; mt<2; mt++)
            LDA(xs, XLD, m0 + mt*16 + g, kb, Ah[mt], Al[mt]);
        uint32_t Bh[4][2], Bl[4][2];
        #pragma unroll
        for (int nt=0; nt<4; nt++)
            LDB(ws, XLD, n0 + nt*8 + g, kb, Bh[nt], Bl[nt]);
        #pragma unroll
        for (int nt=0; nt<4; nt++)
            #pragma unroll
            for (int mt=0; mt<2; mt++)
                mma_bf16(acc[mt][nt], Ah[mt], Bh[nt]);
        #pragma unroll
        for (int nt=0; nt<4; nt++)
            #pragma unroll
            for (int mt=0; mt<2; mt++)
                mma_bf16(acc[mt][nt], Al[mt], Bh[nt]);
        #pragma unroll
        for (int nt=0; nt<4; nt++)
            #pragma unroll
            for (int mt=0; mt<2; mt++)
                mma_bf16(acc[mt][nt], Ah[mt], Bl[nt]);
    }

    #pragma unroll
    for (int mt=0; mt<2; mt++) {
        size_t rl = row0 + m0 + mt*16 + g;
        size_t rh = rl + 8;
        #pragma unroll
        for (int nt=0; nt<4; nt++) {
            int cl = n0 + nt*8 + 2*tg;
            float2 v0, v1;
            if (MODE == 1) {
                v0 = make_float2(sigf(acc[mt][nt][0]), sigf(acc[mt][nt][1]));
                v1 = make_float2(sigf(acc[mt][nt][2]), sigf(acc[mt][nt][3]));
            } else {
                float2 el = *(const float2*)(extra + rl*C_ + cl);
                float2 eh = *(const float2*)(extra + rh*C_ + cl);
                v0 = make_float2(el.x*acc[mt][nt][0], el.y*acc[mt][nt][1]);
                v1 = make_float2(eh.x*acc[mt][nt][2], eh.y*acc[mt][nt][3]);
            }
            *(float2*)(Y + rl*C_ + cl) = v0;
            *(float2*)(Y + rh*C_ + cl) = v1;
        }
    }
}

// ---------------------------------------------------------------------------
// triangle einsum per channel: Ot[c][i][j] = sum_k At[c][i][k]*Bt[c][j][k]
// 256 thr, 8 warps (2M x 4N), warp tile 64x32, chunks of 16 kk, double-buffer.
// Term-major MMA ordering.
// ---------------------------------------------------------------------------
__global__ __launch_bounds__(256, 2) void tri_mma(
    const uint2* __restrict__ Atp, const uint2* __restrict__ Btp,
    float* __restrict__ Ot)
{
    extern __shared__ uint2 smu[];
    uint2* as = smu;                 // [2][128][TLD]
    uint2* bs = smu + 2*SSTG;

    int t = threadIdx.x, warp = t>>5, lane = t&31, g = lane>>2, tg = lane&3;
    size_t coff2 = (size_t)blockIdx.z * (NN_/2);
    const uint2* A = Atp + coff2 + (size_t)blockIdx.y * 128 * (N_/2);
    const uint2* B = Btp + coff2 + (size_t)blockIdx.x * 128 * (N_/2);
    int m0 = (warp & 1) * 64;
    int n0 = (warp >> 1) * 32;

    auto stage = [&](int ch, int s) {
        uint2* ad = as + s*SSTG;
        uint2* bd = bs + s*SSTG;
        #pragma unroll
        for (int i = 0; i < 4; i++) {
            int e = i*256 + t;       // 0..1023 16B chunks per matrix
            int r = e >> 3, q = (e & 7) * 2;
            cp16(ad + r*TLD + q, A + (size_t)r*(N_/2) + ch*16 + q);
            cp16(bd + r*TLD + q, B + (size_t)r*(N_/2) + ch*16 + q);
        }
        cp_commit();
    };

    float acc[4][4][4];
    #pragma unroll
    for (int mt=0; mt<4; mt++)
        #pragma unroll
        for (int nt=0; nt<4; nt++)
            #pragma unroll
            for (int q=0; q<4; q++) acc[mt][nt][q]=0.f;

    stage(0, 0);
    #pragma unroll 1
    for (int ch = 0; ch < 16; ch++) {
        if (ch < 15) {
            stage(ch + 1, (ch + 1) & 1);
            asm volatile("cp.async.wait_group 1;\n");
        } else {
            asm volatile("cp.async.wait_group 0;\n");
        }
        __syncthreads();
        const uint2* ap = as + (ch & 1)*SSTG;
        const uint2* bp = bs + (ch & 1)*SSTG;
        #pragma unroll
        for (int ks = 0; ks < 2; ks++) {
            int kb = ks*8 + tg;
            uint32_t Ah[4][4], Al[4][4];
            #pragma unroll
            for (int mt=0; mt<4; mt++)
                LDA(ap, TLD, m0 + mt*16 + g, kb, Ah[mt], Al[mt]);
            uint32_t Bh[4][2], Bl[4][2];
            #pragma unroll
            for (int nt=0; nt<4; nt++)
                LDB(bp, TLD, n0 + nt*8 + g, kb, Bh[nt], Bl[nt]);
            #pragma unroll
            for (int nt=0; nt<4; nt++)
                #pragma unroll
                for (int mt=0; mt<4; mt++)
                    mma_bf16(acc[mt][nt], Ah[mt], Bh[nt]);
            #pragma unroll
            for (int nt=0; nt<4; nt++)
                #pragma unroll
                for (int mt=0; mt<4; mt++)
                    mma_bf16(acc[mt][nt], Al[mt], Bh[nt]);
            #pragma unroll
            for (int nt=0; nt<4; nt++)
                #pragma unroll
                for (int mt=0; mt<4; mt++)
                    mma_bf16(acc[mt][nt], Ah[mt], Bl[nt]);
        }
        __syncthreads();
    }

    float* O = Ot + (size_t)blockIdx.z * NN_;
    int ib = blockIdx.y * 128 + m0;
    int jb = blockIdx.x * 128 + n0;
    #pragma unroll
    for (int mt=0; mt<4; mt++) {
        int r = ib + mt*16 + g;
        #pragma unroll
        for (int nt=0; nt<4; nt++) {
            int cl = jb + nt*8 + 2*tg;
            *(float2*)(O + (size_t)r*N_ + cl)     = make_float2(acc[mt][nt][0], acc[mt][nt][1]);
            *(float2*)(O + (size_t)(r+8)*N_ + cl) = make_float2(acc[mt][nt][2], acc[mt][nt][3]);
        }
    }
}

// ---------------------------------------------------------------------------
extern "C" void kernel_launch(void* const* d_in, const int* in_sizes, int n_in,
                              void* d_out, int out_size)
{
    const float* z      = (const float*)d_in[0];
    const float* mask   = (const float*)d_in[1];
    const float* ln_i_w = (const float*)d_in[2];
    const float* ln_i_b = (const float*)d_in[3];
    const float* ln_o_w = (const float*)d_in[4];
    const float* ln_o_b = (const float*)d_in[5];
    const float* w_pa   = (const float*)d_in[6];
    const float* w_pb   = (const float*)d_in[7];
    const float* w_ga   = (const float*)d_in[8];
    const float* w_gb   = (const float*)d_in[9];
    const float* w_g    = (const float*)d_in[10];
    const float* w_o    = (const float*)d_in[11];
    float* out = (float*)d_out;

    uint2 *znp, *atp, *btp, *wp;
    float *gt, *ot, *o;
    cudaGetSymbolAddress((void**)&znp, g_znp);
    cudaGetSymbolAddress((void**)&atp, g_atp);
    cudaGetSymbolAddress((void**)&btp, g_btp);
    cudaGetSymbolAddress((void**)&gt,  g_gt);
    cudaGetSymbolAddress((void**)&ot,  g_ot);
    cudaGetSymbolAddress((void**)&o,   g_o);
    cudaGetSymbolAddress((void**)&wp,  g_wp);
    uint2* onp = znp;   // reuse: znp dead after projections

    const int SMEM_D = 3*128*XLD*8;   // 202752
    const int SMEM_S = 2*128*XLD*8;   // 135168
    const int SMEM_T = 4*SSTG*8;      // 73728
    cudaFuncSetAttribute(proj_dual,      cudaFuncAttributeMaxDynamicSharedMemorySize, SMEM_D);
    cudaFuncSetAttribute(proj_single<1>, cudaFuncAttributeMaxDynamicSharedMemorySize, SMEM_S);
    cudaFuncSetAttribute(proj_single<2>, cudaFuncAttributeMaxDynamicSharedMemorySize, SMEM_S);
    cudaFuncSetAttribute(tri_mma,        cudaFuncAttributeMaxDynamicSharedMemorySize, SMEM_T);

    // 0) pre-split weights into packed bf16 hi/lo
    split_w_kernel<<<dim3(32, 6), 256>>>(w_ga, w_pa, w_gb, w_pb, w_g, w_o, wp);
    // 1) znp = packed LN(z)
    ln_pack_kernel<<<NN_, 128>>>(z, ln_i_w, ln_i_b, znp);
    // 2) atp = packed c-major( mask * sigmoid(zn@w_ga^T) * (zn@w_pa^T) )
    proj_dual<<<NN_/128, 512, SMEM_D>>>(znp, wp + 0*C_*KK_, wp + 1*C_*KK_, mask, atp);
    // 3) btp = packed c-major( mask * sigmoid(zn@w_gb^T) * (zn@w_pb^T) )
    proj_dual<<<NN_/128, 512, SMEM_D>>>(znp, wp + 2*C_*KK_, wp + 3*C_*KK_, mask, btp);
    // 4) gate = sigmoid(zn@w_g^T)  fp32 row-major
    proj_single<1><<<NN_/128, 512, SMEM_S>>>(znp, wp + 4*C_*KK_, nullptr, gt);
    // 5) Ot[c][i][j] = sum_k At[c][i][k]*Bt[c][j][k]
    tri_mma<<<dim3(N_/128, N_/128, C_), 256, SMEM_T>>>(atp, btp, ot);
    // 6) o = row-major(ot)
    transpose_kernel<<<dim3(NN_/32, C_/32), dim3(32, 8)>>>(ot, o, C_, NN_);
    // 7) onp = packed LN(o)
    ln_pack_kernel<<<NN_, 128>>>(o, ln_o_w, ln_o_b, onp);
    // 8) out = gate .* (on @ w_o^T)
    proj_single<2><<<NN_/128, 512, SMEM_S>>>(onp, wp + 5*C_*KK_, gt, out);
}

// round 8
// speedup vs baseline: 1.1497x; 1.1497x over previous
#include <cuda_runtime.h>
#include <cstdint>

#define N_  512
#define C_  128
#define NN_ (N_*N_)

// ---------------------------------------------------------------------------
// global scratch: bf16 planes stored as uint32 = bf16x2 (consecutive k pair)
// ---------------------------------------------------------------------------
__device__ uint32_t g_znh[(size_t)NN_*64];      // LN(z) hi plane, [row][k/2]; reused for LN(o)
__device__ uint32_t g_znl[(size_t)NN_*64];
__device__ uint32_t g_ath[(size_t)C_*(NN_/2)];  // a hi, c-major [c][(i*512+k)/2]
__device__ uint32_t g_atl[(size_t)C_*(NN_/2)];
__device__ uint32_t g_bth[(size_t)C_*(NN_/2)];
__device__ uint32_t g_btl[(size_t)C_*(NN_/2)];
__device__ uint32_t g_wh [6*C_*64];             // weight planes [which][n][k/2]
__device__ uint32_t g_wl [6*C_*64];
__device__ float    g_gt [(size_t)NN_*C_];      // gate fp32 row-major
__device__ float    g_ot [(size_t)C_*NN_];      // einsum out fp32, c-major [c][i*512+j]

// ---------------------------------------------------------------------------
__device__ __forceinline__ float sigf(float x) { return 1.f / (1.f + __expf(-x)); }

// pack two fp32 into (hi bf16x2, lo bf16x2); low half = x0
__device__ __forceinline__ uint2 pack_split(float x0, float x1) {
    uint32_t h, l;
    asm("cvt.rn.bf16x2.f32 %0, %1, %2;" : "=r"(h) : "f"(x1), "f"(x0));
    float h0 = __uint_as_float(h << 16);
    float h1 = __uint_as_float(h & 0xffff0000u);
    float r0 = x0 - h0, r1 = x1 - h1;
    asm("cvt.rn.bf16x2.f32 %0, %1, %2;" : "=r"(l) : "f"(r1), "f"(r0));
    return make_uint2(h, l);
}

__device__ __forceinline__ void mma_bf16(float* c, const uint32_t* a, const uint32_t* b) {
    asm volatile(
        "mma.sync.aligned.m16n8k16.row.col.f32.bf16.bf16.f32 "
        "{%0,%1,%2,%3},{%4,%5,%6,%7},{%8,%9},{%0,%1,%2,%3};\n"
        : "+f"(c[0]), "+f"(c[1]), "+f"(c[2]), "+f"(c[3])
        : "r"(a[0]), "r"(a[1]), "r"(a[2]), "r"(a[3]), "r"(b[0]), "r"(b[1]));
}

__device__ __forceinline__ uint32_t smem_u32(const void* p) {
    uint32_t a;
    asm("{ .reg .u64 t; cvta.to.shared.u64 t, %1; cvt.u32.u64 %0, t; }" : "=r"(a) : "l"(p));
    return a;
}
__device__ __forceinline__ void cp16s(uint32_t saddr, const void* g) {
    asm volatile("cp.async.cg.shared.global [%0], [%1], 16;\n" :: "r"(saddr), "l"(g));
}
__device__ __forceinline__ void cp_commit() { asm volatile("cp.async.commit_group;\n"); }
#define CP_WAIT(n) asm volatile("cp.async.wait_group %0;\n" :: "n"(n))

__device__ __forceinline__ void ldm_x4(uint32_t* r, uint32_t addr) {
    asm volatile("ldmatrix.sync.aligned.m8n8.x4.shared.b16 {%0,%1,%2,%3}, [%4];"
        : "=r"(r[0]), "=r"(r[1]), "=r"(r[2]), "=r"(r[3]) : "r"(addr));
}

// 3-term split MMA: acc += Ah*Bh + Al*Bh + Ah*Bl
#define MMA3T(acc, AH, AL, BH, BL) do {  \
    mma_bf16(acc, AH, BH);               \
    mma_bf16(acc, AL, BH);               \
    mma_bf16(acc, AH, BL);               \
} while (0)

// ---------------------------------------------------------------------------
// weight split -> planes.  order: ga=0, pa=1, gb=2, pb=3, g=4, o=5
// ---------------------------------------------------------------------------
__global__ __launch_bounds__(256) void split_w_lm(
    const float* __restrict__ w0, const float* __restrict__ w1,
    const float* __restrict__ w2, const float* __restrict__ w3,
    const float* __restrict__ w4, const float* __restrict__ w5,
    uint32_t* __restrict__ wh, uint32_t* __restrict__ wl)
{
    int which = blockIdx.y;
    const float* w = which==0?w0 : which==1?w1 : which==2?w2 :
                     which==3?w3 : which==4?w4 : w5;
    int e = blockIdx.x*256 + threadIdx.x;      // pair index 0..8191
    int n = e >> 6, kk = e & 63;
    uint2 ps = pack_split(w[n*C_ + 2*kk], w[n*C_ + 2*kk + 1]);
    wh[which*C_*64 + e] = ps.x;
    wl[which*C_*64 + e] = ps.y;
}

// ---------------------------------------------------------------------------
// LayerNorm (row-major fp32 in) -> hi/lo planes [row][k/2]
// ---------------------------------------------------------------------------
__global__ __launch_bounds__(128) void ln_plane(
    const float* __restrict__ x, const float* __restrict__ w,
    const float* __restrict__ b,
    uint32_t* __restrict__ yh, uint32_t* __restrict__ yl)
{
    size_t row = blockIdx.x;
    int c = threadIdx.x;
    float v = x[row*C_ + c];
    float s = v, s2 = v*v;
    #pragma unroll
    for (int o = 16; o; o >>= 1) {
        s  += __shfl_xor_sync(0xffffffffu, s, o);
        s2 += __shfl_xor_sync(0xffffffffu, s2, o);
    }
    __shared__ float sh[8];
    int wid = c >> 5;
    if ((c & 31) == 0) { sh[wid] = s; sh[wid + 4] = s2; }
    __syncthreads();
    s  = sh[0] + sh[1] + sh[2] + sh[3];
    s2 = sh[4] + sh[5] + sh[6] + sh[7];
    float mu  = s  * (1.0f / C_);
    float var = s2 * (1.0f / C_) - mu * mu;
    float inv = rsqrtf(var + 1e-5f);
    float yv = (v - mu) * inv * w[c] + b[c];
    float yn = __shfl_down_sync(0xffffffffu, yv, 1);
    if ((c & 1) == 0) {
        uint2 ps = pack_split(yv, yn);
        yh[row*64 + (c >> 1)] = ps.x;
        yl[row*64 + (c >> 1)] = ps.y;
    }
}

// ---------------------------------------------------------------------------
// fused transpose + LayerNorm + pack:  ot (c-major fp32) -> planes [ij][c/2]
// block = 64 ij columns, 256 threads
// ---------------------------------------------------------------------------
__global__ __launch_bounds__(256) void ln_cmajor(
    const float* __restrict__ ot, const float* __restrict__ w,
    const float* __restrict__ b,
    uint32_t* __restrict__ yh, uint32_t* __restrict__ yl)
{
    __shared__ float s[128][65];
    __shared__ float ps [4][64], ps2[4][64];
    __shared__ float wsb[256];
    __shared__ float muv[128];
    int t = threadIdx.x;
    size_t ij0 = (size_t)blockIdx.x * 64;

    #pragma unroll
    for (int i = 0; i < 8; i++) {
        int e = i*256 + t;              // 0..2047
        int c = e >> 4, x4 = e & 15;
        float4 v = *(const float4*)(ot + (size_t)c*NN_ + ij0 + x4*4);
        s[c][x4*4]   = v.x; s[c][x4*4+1] = v.y;
        s[c][x4*4+2] = v.z; s[c][x4*4+3] = v.w;
    }
    if (t < 128) { wsb[t] = w[t]; wsb[128 + t] = b[t]; }
    __syncthreads();

    {   // partial sums over c quarters
        int ij = t & 63, cq = t >> 6;
        float sm = 0.f, sq = 0.f;
        #pragma unroll
        for (int c = cq*32; c < cq*32 + 32; c++) {
            float v = s[c][ij];
            sm += v; sq += v*v;
        }
        ps[cq][ij] = sm; ps2[cq][ij] = sq;
    }
    __syncthreads();
    if (t < 64) {
        float sm = ps[0][t] + ps[1][t] + ps[2][t] + ps[3][t];
        float sq = ps2[0][t] + ps2[1][t] + ps2[2][t] + ps2[3][t];
        float mu = sm * (1.0f/C_);
        float var = sq * (1.0f/C_) - mu*mu;
        muv[t] = mu;
        muv[64 + t] = rsqrtf(var + 1e-5f);
    }
    __syncthreads();

    #pragma unroll
    for (int i = 0; i < 16; i++) {
        int e = i*256 + t;              // 0..4095
        int ij = e >> 6, kk = e & 63;
        float mu = muv[ij], inv = muv[64 + ij];
        int c0 = 2*kk;
        float y0 = (s[c0][ij]   - mu) * inv * wsb[c0]   + wsb[128 + c0];
        float y1 = (s[c0+1][ij] - mu) * inv * wsb[c0+1] + wsb[128 + c0 + 1];
        uint2 p = pack_split(y0, y1);
        yh[(ij0 + ij)*64 + kk] = p.x;
        yl[(ij0 + ij)*64 + kk] = p.y;
    }
}

// ---------------------------------------------------------------------------
// proj_dual: D = X @ [W1|W2]^T via ldmatrix + 3x bf16, k-pipelined.
// 512 thr, 16 warps (4M x 4N), warp 32x32 per GEMM, M=128 rows, 4 k-stages.
// epilogue: y = mask * sigmoid(D1) * D2 -> c-major hi/lo planes.
// ---------------------------------------------------------------------------
#define SROW   80
#define PLANE_ (128*SROW)            // 10240 B
#define PD_STAGE (6*PLANE_)          // 61440
#define PD_SMEM  (2*PD_STAGE)        // 122880

__global__ __launch_bounds__(512, 1) void proj_dual_lm(
    const uint32_t* __restrict__ Xh, const uint32_t* __restrict__ Xl,
    const uint32_t* __restrict__ W1h, const uint32_t* __restrict__ W1l,
    const uint32_t* __restrict__ W2h, const uint32_t* __restrict__ W2l,
    const float* __restrict__ mask,
    uint32_t* __restrict__ Yh, uint32_t* __restrict__ Yl)
{
    extern __shared__ char smraw[];
    uint32_t sb = smem_u32(smraw);
    int t = threadIdx.x, warp = t>>5, lane = t&31, g = lane>>2, tg = lane&3;
    size_t row0 = (size_t)blockIdx.x * 128;
    int m0 = (warp & 3) * 32, n0 = (warp >> 2) * 32;

    const char* p0 = (const char*)(Xh + row0*64);
    const char* p1 = (const char*)(Xl + row0*64);
    const char* p2 = (const char*)W1h;
    const char* p3 = (const char*)W1l;
    const char* p4 = (const char*)W2h;
    const char* p5 = (const char*)W2l;

    int lr = t >> 2, lch = (t & 3) * 16;          // loader: row, chunk byte
    auto load_stage = [&](int st, int slot) {
        uint32_t d = sb + slot*PD_STAGE + lr*SROW + lch;
        int go = lr*256 + st*64 + lch;
        cp16s(d,            p0 + go);
        cp16s(d + PLANE_,   p1 + go);
        cp16s(d + 2*PLANE_, p2 + go);
        cp16s(d + 3*PLANE_, p3 + go);
        cp16s(d + 4*PLANE_, p4 + go);
        cp16s(d + 5*PLANE_, p5 + go);
        cp_commit();
    };

    float acc1[2][4][4], acc2[2][4][4];
    #pragma unroll
    for (int mt=0; mt<2; mt++)
        #pragma unroll
        for (int nt=0; nt<4; nt++)
            #pragma unroll
            for (int q=0; q<4; q++) { acc1[mt][nt][q]=0.f; acc2[mt][nt][q]=0.f; }

    int l16 = lane & 15;
    uint32_t coff = (uint32_t)((lane >> 4) * 16);

    load_stage(0, 0);
    load_stage(1, 1);

    #pragma unroll 1
    for (int st = 0; st < 4; st++) {
        if (st < 3) CP_WAIT(1); else CP_WAIT(0);
        __syncthreads();
        uint32_t base = sb + (st & 1)*PD_STAGE;
        #pragma unroll
        for (int kc = 0; kc < 2; kc++) {
            uint32_t kb = coff + kc*32;
            uint32_t Ah[2][4], Al[2][4];
            #pragma unroll
            for (int mt=0; mt<2; mt++) {
                uint32_t ar = (uint32_t)((m0 + mt*16 + l16) * SROW) + kb;
                ldm_x4(Ah[mt], base + ar);
                ldm_x4(Al[mt], base + PLANE_ + ar);
            }
            #pragma unroll
            for (int np=0; np<2; np++) {
                uint32_t br = (uint32_t)((n0 + np*16 + l16) * SROW) + kb;
                uint32_t B[4], Bl_[4];
                // GEMM1
                ldm_x4(B,   base + 2*PLANE_ + br);
                ldm_x4(Bl_, base + 3*PLANE_ + br);
                #pragma unroll
                for (int h=0; h<2; h++) {
                    uint32_t bh[2] = {B[h], B[2+h]}, bl[2] = {Bl_[h], Bl_[2+h]};
                    int nt = np*2 + h;
                    #pragma unroll
                    for (int mt=0; mt<2; mt++)
                        MMA3T(acc1[mt][nt], Ah[mt], Al[mt], bh, bl);
                }
                // GEMM2
                ldm_x4(B,   base + 4*PLANE_ + br);
                ldm_x4(Bl_, base + 5*PLANE_ + br);
                #pragma unroll
                for (int h=0; h<2; h++) {
                    uint32_t bh[2] = {B[h], B[2+h]}, bl[2] = {Bl_[h], Bl_[2+h]};
                    int nt = np*2 + h;
                    #pragma unroll
                    for (int mt=0; mt<2; mt++)
                        MMA3T(acc2[mt][nt], Ah[mt], Al[mt], bh, bl);
                }
            }
        }
        __syncthreads();
        if (st + 2 < 4) load_stage(st + 2, st & 1);
    }

    // epilogue via smem fp32 tile [128][132]
    float* so = (float*)smraw;
    #pragma unroll
    for (int mt=0; mt<2; mt++) {
        int rl = m0 + mt*16 + g, rh = rl + 8;
        float ml = mask[row0 + rl], mh = mask[row0 + rh];
        #pragma unroll
        for (int nt=0; nt<4; nt++) {
            int cl = n0 + nt*8 + 2*tg;
            so[rl*132 + cl]     = ml * sigf(acc1[mt][nt][0]) * acc2[mt][nt][0];
            so[rl*132 + cl + 1] = ml * sigf(acc1[mt][nt][1]) * acc2[mt][nt][1];
            so[rh*132 + cl]     = mh * sigf(acc1[mt][nt][2]) * acc2[mt][nt][2];
            so[rh*132 + cl + 1] = mh * sigf(acc1[mt][nt][3]) * acc2[mt][nt][3];
        }
    }
    __syncthreads();
    int c  = t >> 2;
    int pp0 = (t & 3) * 16;
    size_t ubase = (size_t)c * (NN_/2) + row0/2;
    #pragma unroll
    for (int p = 0; p < 16; p++) {
        int pr = pp0 + p;
        uint2 psv = pack_split(so[(2*pr)*132 + c], so[(2*pr+1)*132 + c]);
        Yh[ubase + pr] = psv.x;
        Yl[ubase + pr] = psv.y;
    }
}

// ---------------------------------------------------------------------------
// proj_single: D = X@W^T.  MODE 0: Y = sigmoid(D); MODE 1: Y = extra .* D
// same skeleton, 4 planes, fp32 row-major output.
// ---------------------------------------------------------------------------
#define PS_STAGE (4*PLANE_)          // 40960
#define PS_SMEM  (2*PS_STAGE)        // 81920

template<int MODE>
__global__ __launch_bounds__(512, 1) void proj_single_lm(
    const uint32_t* __restrict__ Xh, const uint32_t* __restrict__ Xl,
    const uint32_t* __restrict__ Wh, const uint32_t* __restrict__ Wl,
    const float* __restrict__ extra, float* __restrict__ Y)
{
    extern __shared__ char smraw[];
    uint32_t sb = smem_u32(smraw);
    int t = threadIdx.x, warp = t>>5, lane = t&31, g = lane>>2, tg = lane&3;
    size_t row0 = (size_t)blockIdx.x * 128;
    int m0 = (warp & 3) * 32, n0 = (warp >> 2) * 32;

    const char* p0 = (const char*)(Xh + row0*64);
    const char* p1 = (const char*)(Xl + row0*64);
    const char* p2 = (const char*)Wh;
    const char* p3 = (const char*)Wl;

    int lr = t >> 2, lch = (t & 3) * 16;
    auto load_stage = [&](int st, int slot) {
        uint32_t d = sb + slot*PS_STAGE + lr*SROW + lch;
        int go = lr*256 + st*64 + lch;
        cp16s(d,            p0 + go);
        cp16s(d + PLANE_,   p1 + go);
        cp16s(d + 2*PLANE_, p2 + go);
        cp16s(d + 3*PLANE_, p3 + go);
        cp_commit();
    };

    float acc[2][4][4];
    #pragma unroll
    for (int mt=0; mt<2; mt++)
        #pragma unroll
        for (int nt=0; nt<4; nt++)
            #pragma unroll
            for (int q=0; q<4; q++) acc[mt][nt][q]=0.f;

    int l16 = lane & 15;
    uint32_t coff = (uint32_t)((lane >> 4) * 16);

    load_stage(0, 0);
    load_stage(1, 1);

    #pragma unroll 1
    for (int st = 0; st < 4; st++) {
        if (st < 3) CP_WAIT(1); else CP_WAIT(0);
        __syncthreads();
        uint32_t base = sb + (st & 1)*PS_STAGE;
        #pragma unroll
        for (int kc = 0; kc < 2; kc++) {
            uint32_t kb = coff + kc*32;
            uint32_t Ah[2][4], Al[2][4];
            #pragma unroll
            for (int mt=0; mt<2; mt++) {
                uint32_t ar = (uint32_t)((m0 + mt*16 + l16) * SROW) + kb;
                ldm_x4(Ah[mt], base + ar);
                ldm_x4(Al[mt], base + PLANE_ + ar);
            }
            #pragma unroll
            for (int np=0; np<2; np++) {
                uint32_t br = (uint32_t)((n0 + np*16 + l16) * SROW) + kb;
                uint32_t B[4], Bl_[4];
                ldm_x4(B,   base + 2*PLANE_ + br);
                ldm_x4(Bl_, base + 3*PLANE_ + br);
                #pragma unroll
                for (int h=0; h<2; h++) {
                    uint32_t bh[2] = {B[h], B[2+h]}, bl[2] = {Bl_[h], Bl_[2+h]};
                    int nt = np*2 + h;
                    #pragma unroll
                    for (int mt=0; mt<2; mt++)
                        MMA3T(acc[mt][nt], Ah[mt], Al[mt], bh, bl);
                }
            }
        }
        __syncthreads();
        if (st + 2 < 4) load_stage(st + 2, st & 1);
    }

    #pragma unroll
    for (int mt=0; mt<2; mt++) {
        size_t rl = row0 + m0 + mt*16 + g;
        size_t rh = rl + 8;
        #pragma unroll
        for (int nt=0; nt<4; nt++) {
            int cl = n0 + nt*8 + 2*tg;
            float2 v0, v1;
            if (MODE == 0) {
                v0 = make_float2(sigf(acc[mt][nt][0]), sigf(acc[mt][nt][1]));
                v1 = make_float2(sigf(acc[mt][nt][2]), sigf(acc[mt][nt][3]));
            } else {
                float2 el = *(const float2*)(extra + rl*C_ + cl);
                float2 eh = *(const float2*)(extra + rh*C_ + cl);
                v0 = make_float2(el.x*acc[mt][nt][0], el.y*acc[mt][nt][1]);
                v1 = make_float2(eh.x*acc[mt][nt][2], eh.y*acc[mt][nt][3]);
            }
            *(float2*)(Y + rl*C_ + cl) = v0;
            *(float2*)(Y + rh*C_ + cl) = v1;
        }
    }
}

// ---------------------------------------------------------------------------
// tri: per channel cz, Ot[i][j] = sum_k A[i,k]*B[j,k]; 128x128 tile, K=512
// in 16 stages of k32; 256 thr, 8 warps (4M x 2N), warp 32 x 64; 2 CTAs/SM.
// ---------------------------------------------------------------------------
#define TR_STAGE (4*PLANE_)          // 40960
#define TR_SMEM  (2*TR_STAGE)        // 81920

__global__ __launch_bounds__(256, 2) void tri_lm(
    const uint32_t* __restrict__ AhG, const uint32_t* __restrict__ AlG,
    const uint32_t* __restrict__ BhG, const uint32_t* __restrict__ BlG,
    float* __restrict__ Ot)
{
    extern __shared__ char smraw[];
    uint32_t sb = smem_u32(smraw);
    int t = threadIdx.x, warp = t>>5, lane = t&31, g = lane>>2, tg = lane&3;
    int j0 = blockIdx.x * 128, i0 = blockIdx.y * 128, cz = blockIdx.z;
    int m0 = (warp & 3) * 32, n0 = (warp >> 2) * 64;

    size_t cb = (size_t)cz * (NN_/2);
    const char* p0 = (const char*)(AhG + cb + (size_t)i0*256);
    const char* p1 = (const char*)(AlG + cb + (size_t)i0*256);
    const char* p2 = (const char*)(BhG + cb + (size_t)j0*256);
    const char* p3 = (const char*)(BlG + cb + (size_t)j0*256);

    // loader: 4 planes x 128 rows x 4 chunks = 2048 cp16 / 256 thr = 8
    int lr = (t >> 1) & 127;                 // row (two threads per row)
    int lc2 = (t & 1) * 32;                  // chunk pair base byte
    auto load_stage = [&](int st, int slot) {
        uint32_t d = sb + slot*TR_STAGE + lr*SROW + lc2;
        size_t go = (size_t)lr*1024 + st*64 + lc2;
        cp16s(d,                 p0 + go);
        cp16s(d + 16,            p0 + go + 16);
        cp16s(d + PLANE_,        p1 + go);
        cp16s(d + PLANE_ + 16,   p1 + go + 16);
        cp16s(d + 2*PLANE_,      p2 + go);
        cp16s(d + 2*PLANE_ + 16, p2 + go + 16);
        cp16s(d + 3*PLANE_,      p3 + go);
        cp16s(d + 3*PLANE_ + 16, p3 + go + 16);
        cp_commit();
    };

    float acc[2][8][4];
    #pragma unroll
    for (int mt=0; mt<2; mt++)
        #pragma unroll
        for (int nt=0; nt<8; nt++)
            #pragma unroll
            for (int q=0; q<4; q++) acc[mt][nt][q]=0.f;

    int l16 = lane & 15;
    uint32_t coff = (uint32_t)((lane >> 4) * 16);

    load_stage(0, 0);
    load_stage(1, 1);

    #pragma unroll 1
    for (int st = 0; st < 16; st++) {
        if (st < 15) CP_WAIT(1); else CP_WAIT(0);
        __syncthreads();
        uint32_t base = sb + (st & 1)*TR_STAGE;
        #pragma unroll
        for (int kc = 0; kc < 2; kc++) {
            uint32_t kb = coff + kc*32;
            uint32_t Ah[2][4], Al[2][4];
            #pragma unroll
            for (int mt=0; mt<2; mt++) {
                uint32_t ar = (uint32_t)((m0 + mt*16 + l16) * SROW) + kb;
                ldm_x4(Ah[mt], base + ar);
                ldm_x4(Al[mt], base + PLANE_ + ar);
            }
            #pragma unroll
            for (int np=0; np<4; np++) {
                uint32_t br = (uint32_t)((n0 + np*16 + l16) * SROW) + kb;
                uint32_t B[4], Bl_[4];
                ldm_x4(B,   base + 2*PLANE_ + br);
                ldm_x4(Bl_, base + 3*PLANE_ + br);
                #pragma unroll
                for (int h=0; h<2; h++) {
                    uint32_t bh[2] = {B[h], B[2+h]}, bl[2] = {Bl_[h], Bl_[2+h]};
                    int nt = np*2 + h;
                    #pragma unroll
                    for (int mt=0; mt<2; mt++)
                        MMA3T(acc[mt][nt], Ah[mt], Al[mt], bh, bl);
                }
            }
        }
        __syncthreads();
        if (st + 2 < 16) load_stage(st + 2, st & 1);
    }

    float* O = Ot + (size_t)cz*NN_;
    #pragma unroll
    for (int mt=0; mt<2; mt++) {
        int r = i0 + m0 + mt*16 + g;
        #pragma unroll
        for (int nt=0; nt<8; nt++) {
            int cl = j0 + n0 + nt*8 + 2*tg;
            *(float2*)(O + (size_t)r*N_ + cl)     = make_float2(acc[mt][nt][0], acc[mt][nt][1]);
            *(float2*)(O + (size_t)(r+8)*N_ + cl) = make_float2(acc[mt][nt][2], acc[mt][nt][3]);
        }
    }
}

// ---------------------------------------------------------------------------
extern "C" void kernel_launch(void* const* d_in, const int* in_sizes, int n_in,
                              void* d_out, int out_size)
{
    const float* z      = (const float*)d_in[0];
    const float* mask   = (const float*)d_in[1];
    const float* ln_i_w = (const float*)d_in[2];
    const float* ln_i_b = (const float*)d_in[3];
    const float* ln_o_w = (const float*)d_in[4];
    const float* ln_o_b = (const float*)d_in[5];
    const float* w_pa   = (const float*)d_in[6];
    const float* w_pb   = (const float*)d_in[7];
    const float* w_ga   = (const float*)d_in[8];
    const float* w_gb   = (const float*)d_in[9];
    const float* w_g    = (const float*)d_in[10];
    const float* w_o    = (const float*)d_in[11];
    float* out = (float*)d_out;

    uint32_t *znh, *znl, *ath, *atl, *bth, *btl, *wh, *wl;
    float *gt, *ot;
    cudaGetSymbolAddress((void**)&znh, g_znh);
    cudaGetSymbolAddress((void**)&znl, g_znl);
    cudaGetSymbolAddress((void**)&ath, g_ath);
    cudaGetSymbolAddress((void**)&atl, g_atl);
    cudaGetSymbolAddress((void**)&bth, g_bth);
    cudaGetSymbolAddress((void**)&btl, g_btl);
    cudaGetSymbolAddress((void**)&wh,  g_wh);
    cudaGetSymbolAddress((void**)&wl,  g_wl);
    cudaGetSymbolAddress((void**)&gt,  g_gt);
    cudaGetSymbolAddress((void**)&ot,  g_ot);

    cudaFuncSetAttribute(proj_dual_lm,      cudaFuncAttributeMaxDynamicSharedMemorySize, PD_SMEM);
    cudaFuncSetAttribute(proj_single_lm<0>, cudaFuncAttributeMaxDynamicSharedMemorySize, PS_SMEM);
    cudaFuncSetAttribute(proj_single_lm<1>, cudaFuncAttributeMaxDynamicSharedMemorySize, PS_SMEM);
    cudaFuncSetAttribute(tri_lm,            cudaFuncAttributeMaxDynamicSharedMemorySize, TR_SMEM);

    // weight plane order: ga=0, pa=1, gb=2, pb=3, g=4, o=5
    split_w_lm<<<dim3(32, 6), 256>>>(w_ga, w_pa, w_gb, w_pb, w_g, w_o, wh, wl);
    // zn planes
    ln_plane<<<NN_, 128>>>(z, ln_i_w, ln_i_b, znh, znl);
    // a = mask * sig(zn@ga^T) * (zn@pa^T)  -> c-major planes
    proj_dual_lm<<<NN_/128, 512, PD_SMEM>>>(znh, znl,
        wh + 0*C_*64, wl + 0*C_*64, wh + 1*C_*64, wl + 1*C_*64, mask, ath, atl);
    // b
    proj_dual_lm<<<NN_/128, 512, PD_SMEM>>>(znh, znl,
        wh + 2*C_*64, wl + 2*C_*64, wh + 3*C_*64, wl + 3*C_*64, mask, bth, btl);
    // gate (fp32 row-major)
    proj_single_lm<0><<<NN_/128, 512, PS_SMEM>>>(znh, znl,
        wh + 4*C_*64, wl + 4*C_*64, nullptr, gt);
    // triangle einsum -> ot c-major fp32
    tri_lm<<<dim3(N_/128, N_/128, C_), 256, TR_SMEM>>>(ath, atl, bth, btl, ot);
    // fused transpose + LN + pack -> on planes (reuse zn planes)
    ln_cmajor<<<NN_/64, 256>>>(ot, ln_o_w, ln_o_b, znh, znl);
    // out = gate .* (on @ wo^T)
    proj_single_lm<1><<<NN_/128, 512, PS_SMEM>>>(znh, znl,
        wh + 5*C_*64, wl + 5*C_*64, gt, out);
}

// round 9
// speedup vs baseline: 1.3010x; 1.1316x over previous
#include <cuda_runtime.h>
#include <cstdint>

#define N_  512
#define C_  128
#define NN_ (N_*N_)

// ---------------------------------------------------------------------------
// global scratch (bf16 planes stored as uint32 = bf16x2 of consecutive k pair)
// ---------------------------------------------------------------------------
__device__ uint32_t g_ath[(size_t)C_*(NN_/2)];  // a hi, c-major [c][(i*512+k)/2]
__device__ uint32_t g_atl[(size_t)C_*(NN_/2)];
__device__ uint32_t g_bth[(size_t)C_*(NN_/2)];
__device__ uint32_t g_btl[(size_t)C_*(NN_/2)];
__device__ uint32_t g_wh [6*C_*64];             // weight planes [which][n][k/2]
__device__ uint32_t g_wl [6*C_*64];
__device__ float    g_gt [(size_t)NN_*C_];      // gate fp32 row-major
__device__ float    g_ot [(size_t)C_*NN_];      // einsum out fp32, c-major

// ---------------------------------------------------------------------------
__device__ __forceinline__ float sigf(float x) { return 1.f / (1.f + __expf(-x)); }

__device__ __forceinline__ uint2 pack_split(float x0, float x1) {
    uint32_t h, l;
    asm("cvt.rn.bf16x2.f32 %0, %1, %2;" : "=r"(h) : "f"(x1), "f"(x0));
    float h0 = __uint_as_float(h << 16);
    float h1 = __uint_as_float(h & 0xffff0000u);
    float r0 = x0 - h0, r1 = x1 - h1;
    asm("cvt.rn.bf16x2.f32 %0, %1, %2;" : "=r"(l) : "f"(r1), "f"(r0));
    return make_uint2(h, l);
}

__device__ __forceinline__ void mma_bf16(float* c, const uint32_t* a, const uint32_t* b) {
    asm volatile(
        "mma.sync.aligned.m16n8k16.row.col.f32.bf16.bf16.f32 "
        "{%0,%1,%2,%3},{%4,%5,%6,%7},{%8,%9},{%0,%1,%2,%3};\n"
        : "+f"(c[0]), "+f"(c[1]), "+f"(c[2]), "+f"(c[3])
        : "r"(a[0]), "r"(a[1]), "r"(a[2]), "r"(a[3]), "r"(b[0]), "r"(b[1]));
}

__device__ __forceinline__ uint32_t smem_u32(const void* p) {
    uint32_t a;
    asm("{ .reg .u64 t; cvta.to.shared.u64 t, %1; cvt.u32.u64 %0, t; }" : "=r"(a) : "l"(p));
    return a;
}
__device__ __forceinline__ void cp16s(uint32_t saddr, const void* g) {
    asm volatile("cp.async.cg.shared.global [%0], [%1], 16;\n" :: "r"(saddr), "l"(g));
}
__device__ __forceinline__ void cp_commit() { asm volatile("cp.async.commit_group;\n"); }
#define CP_WAIT(n) asm volatile("cp.async.wait_group %0;\n" :: "n"(n))

__device__ __forceinline__ void ldm_x4(uint32_t* r, uint32_t addr) {
    asm volatile("ldmatrix.sync.aligned.m8n8.x4.shared.b16 {%0,%1,%2,%3}, [%4];"
        : "=r"(r[0]), "=r"(r[1]), "=r"(r[2]), "=r"(r[3]) : "r"(addr));
}

#define MMA3T(acc, AH, AL, BH, BL) do {  \
    mma_bf16(acc, AH, BH);               \
    mma_bf16(acc, AL, BH);               \
    mma_bf16(acc, AH, BL);               \
} while (0)

// ---------------------------------------------------------------------------
// shared 128x128x128 GEMM body (3-term bf16 split).
// X planes at xb (hi) / xb+XPL (lo); W planes at wb / wb+XPL. Row stride 272B.
// warp tile 32x32, 16 warps (4M x 4N).
// ---------------------------------------------------------------------------
#define XROW 272
#define XPL  34816

__device__ __forceinline__ void gemm128(uint32_t xb, uint32_t wb, float acc[2][4][4],
                                        int m0, int n0, int l16, uint32_t coff)
{
    #pragma unroll
    for (int kc = 0; kc < 8; kc++) {
        uint32_t kb = coff + kc*32;
        uint32_t Ah[2][4], Al[2][4];
        #pragma unroll
        for (int mt = 0; mt < 2; mt++) {
            uint32_t ar = (uint32_t)((m0 + mt*16 + l16) * XROW) + kb;
            ldm_x4(Ah[mt], xb + ar);
            ldm_x4(Al[mt], xb + XPL + ar);
        }
        #pragma unroll
        for (int np = 0; np < 2; np++) {
            uint32_t br = (uint32_t)((n0 + np*16 + l16) * XROW) + kb;
            uint32_t Bh[4], Bl[4];
            ldm_x4(Bh, wb + br);
            ldm_x4(Bl, wb + XPL + br);
            #pragma unroll
            for (int h = 0; h < 2; h++) {
                uint32_t bh[2] = {Bh[h], Bh[2+h]}, bl[2] = {Bl[h], Bl[2+h]};
                int nt = np*2 + h;
                #pragma unroll
                for (int mt = 0; mt < 2; mt++)
                    MMA3T(acc[mt][nt], Ah[mt], Al[mt], bh, bl);
            }
        }
    }
}

// ---------------------------------------------------------------------------
// weight split -> planes.  order: ga=0, pa=1, gb=2, pb=3, g=4, o=5
// ---------------------------------------------------------------------------
__global__ __launch_bounds__(256) void split_w_lm(
    const float* __restrict__ w0, const float* __restrict__ w1,
    const float* __restrict__ w2, const float* __restrict__ w3,
    const float* __restrict__ w4, const float* __restrict__ w5,
    uint32_t* __restrict__ wh, uint32_t* __restrict__ wl)
{
    int which = blockIdx.y;
    const float* w = which==0?w0 : which==1?w1 : which==2?w2 :
                     which==3?w3 : which==4?w4 : w5;
    int e = blockIdx.x*256 + threadIdx.x;
    int n = e >> 6, kk = e & 63;
    uint2 ps = pack_split(w[n*C_ + 2*kk], w[n*C_ + 2*kk + 1]);
    wh[which*C_*64 + e] = ps.x;
    wl[which*C_*64 + e] = ps.y;
}

// ---------------------------------------------------------------------------
// proj_fused: per 128-row tile: LN(z) in smem -> X planes, then 5 GEMMs
// (ga,pa -> a planes c-major; gb,pb -> b planes; g -> gate fp32 row-major)
// smem: X planes [0,69632) | B0 [69632,139264) | B1 [139264,208896) | lnwb 1KB
// ---------------------------------------------------------------------------
#define PJ_B0   69632
#define PJ_B1   139264
#define PJ_WS   208896
#define PJ_SMEM 209920

__global__ __launch_bounds__(512, 1) void proj_fused(
    const float* __restrict__ z, const float* __restrict__ mask,
    const float* __restrict__ lnw, const float* __restrict__ lnb,
    const uint32_t* __restrict__ WH, const uint32_t* __restrict__ WL,
    uint32_t* __restrict__ aH, uint32_t* __restrict__ aL,
    uint32_t* __restrict__ bH, uint32_t* __restrict__ bL,
    float* __restrict__ gate)
{
    extern __shared__ char sm[];
    uint32_t sb = smem_u32(sm);
    int t = threadIdx.x, warp = t>>5, lane = t&31, g = lane>>2, tg = lane&3;
    int l16 = lane & 15;
    uint32_t coff = (uint32_t)((lane >> 4) * 16);
    int m0 = (warp & 3) * 32, n0 = (warp >> 2) * 32;
    size_t row0 = (size_t)blockIdx.x * 128;

    if (t < 128) {
        ((float*)(sm + PJ_WS))[t]       = lnw[t];
        ((float*)(sm + PJ_WS))[128 + t] = lnb[t];
    }

    // load z tile into B0 as [128][132] fp32
    {
        const char* zp = (const char*)(z + row0*C_);
        #pragma unroll
        for (int i = 0; i < 8; i++) {
            int e = i*512 + t, r = e >> 5, c4 = e & 31;
            cp16s(sb + PJ_B0 + (uint32_t)(r*528 + c4*16), zp + (size_t)r*512 + c4*16);
        }
        cp_commit();
    }
    CP_WAIT(0);
    __syncthreads();

    // LN -> X planes (hi at 0, lo at XPL)
    {
        float* s  = (float*)(sm + PJ_B0);
        float* wv = (float*)(sm + PJ_WS);
        int r = t >> 2, q = t & 3;
        float y[32];
        float s1 = 0.f, s2 = 0.f;
        #pragma unroll
        for (int i = 0; i < 32; i++) {
            float v = s[r*132 + q*32 + i];
            y[i] = v; s1 += v; s2 += v*v;
        }
        s1 += __shfl_xor_sync(~0u, s1, 1); s2 += __shfl_xor_sync(~0u, s2, 1);
        s1 += __shfl_xor_sync(~0u, s1, 2); s2 += __shfl_xor_sync(~0u, s2, 2);
        float mu  = s1 * (1.f/128.f);
        float var = s2 * (1.f/128.f) - mu*mu;
        float inv = rsqrtf(var + 1e-5f);
        uint32_t* xh = (uint32_t*)(sm + r*XROW);
        uint32_t* xl = (uint32_t*)(sm + XPL + r*XROW);
        #pragma unroll
        for (int j = 0; j < 16; j++) {
            int c0 = q*32 + 2*j;
            float y0 = (y[2*j]   - mu) * inv * wv[c0]   + wv[128 + c0];
            float y1 = (y[2*j+1] - mu) * inv * wv[c0+1] + wv[128 + c0 + 1];
            uint2 p = pack_split(y0, y1);
            xh[q*16 + j] = p.x;
            xl[q*16 + j] = p.y;
        }
    }
    __syncthreads();

    auto loadW = [&](int which, uint32_t dst) {
        const uint32_t* srcH = WH + which*8192;
        const uint32_t* srcL = WL + which*8192;
        #pragma unroll
        for (int i = 0; i < 8; i++) {
            int e = i*512 + t;               // 0..4095
            int pl = e >> 11, r = (e >> 4) & 127, ch = e & 15;
            const uint32_t* s_ = pl ? srcL : srcH;
            cp16s(dst + (uint32_t)(pl*XPL + r*XROW + ch*16), s_ + (size_t)r*64 + ch*4);
        }
        cp_commit();
    };

    float acc1[2][4][4], acc2[2][4][4];
    auto zacc = [&]() {
        #pragma unroll
        for (int mt = 0; mt < 2; mt++)
            #pragma unroll
            for (int nt = 0; nt < 4; nt++)
                #pragma unroll
                for (int q = 0; q < 4; q++) { acc1[mt][nt][q] = 0.f; acc2[mt][nt][q] = 0.f; }
    };

    // epilogue: y = mask*sig(acc1)*acc2 -> c-major packed planes (tile in B0)
    auto epi_ab = [&](uint32_t* Yh, uint32_t* Yl) {
        __syncthreads();
        float* so = (float*)(sm + PJ_B0);
        #pragma unroll
        for (int mt = 0; mt < 2; mt++) {
            int rl = m0 + mt*16 + g, rh = rl + 8;
            float ml = mask[row0 + rl], mh = mask[row0 + rh];
            #pragma unroll
            for (int nt = 0; nt < 4; nt++) {
                int cl = n0 + nt*8 + 2*tg;
                so[rl*132 + cl]     = ml * sigf(acc1[mt][nt][0]) * acc2[mt][nt][0];
                so[rl*132 + cl + 1] = ml * sigf(acc1[mt][nt][1]) * acc2[mt][nt][1];
                so[rh*132 + cl]     = mh * sigf(acc1[mt][nt][2]) * acc2[mt][nt][2];
                so[rh*132 + cl + 1] = mh * sigf(acc1[mt][nt][3]) * acc2[mt][nt][3];
            }
        }
        __syncthreads();
        int c = t >> 2, p0 = (t & 3) * 16;
        size_t ub = (size_t)c * (NN_/2) + row0/2;
        #pragma unroll
        for (int p = 0; p < 16; p++) {
            int pr = p0 + p;
            uint2 pv = pack_split(so[(2*pr)*132 + c], so[(2*pr+1)*132 + c]);
            Yh[ub + pr] = pv.x;
            Yl[ub + pr] = pv.y;
        }
        __syncthreads();
    };

    // ---- pipeline: ga,pa -> a; gb,pb -> b; g -> gate ----
    loadW(0, sb + PJ_B0);          // ga
    loadW(1, sb + PJ_B1);          // pa
    zacc();
    CP_WAIT(1); __syncthreads();
    gemm128(sb, sb + PJ_B0, acc1, m0, n0, l16, coff);      // ga
    CP_WAIT(0); __syncthreads();
    gemm128(sb, sb + PJ_B1, acc2, m0, n0, l16, coff);      // pa
    __syncthreads();
    loadW(2, sb + PJ_B1);          // gb (pa consumed)
    epi_ab(aH, aL);                // tile in B0 (ga consumed)
    loadW(3, sb + PJ_B0);          // pb (B0 free after epi)
    zacc();
    CP_WAIT(1); __syncthreads();
    gemm128(sb, sb + PJ_B1, acc1, m0, n0, l16, coff);      // gb
    CP_WAIT(0); __syncthreads();
    gemm128(sb, sb + PJ_B0, acc2, m0, n0, l16, coff);      // pb
    __syncthreads();
    loadW(4, sb + PJ_B1);          // wg
    epi_ab(bH, bL);                // tile in B0 (pb consumed)
    zacc();
    CP_WAIT(0); __syncthreads();
    gemm128(sb, sb + PJ_B1, acc1, m0, n0, l16, coff);      // wg

    // gate epilogue: fp32 row-major, direct
    #pragma unroll
    for (int mt = 0; mt < 2; mt++) {
        size_t rl = row0 + m0 + mt*16 + g;
        size_t rh = rl + 8;
        #pragma unroll
        for (int nt = 0; nt < 4; nt++) {
            int cl = n0 + nt*8 + 2*tg;
            *(float2*)(gate + rl*C_ + cl) =
                make_float2(sigf(acc1[mt][nt][0]), sigf(acc1[mt][nt][1]));
            *(float2*)(gate + rh*C_ + cl) =
                make_float2(sigf(acc1[mt][nt][2]), sigf(acc1[mt][nt][3]));
        }
    }
}

// ---------------------------------------------------------------------------
// tri: per channel cz, Ot[i][j] = sum_k A[i,k]*B[j,k]; 128x128 tile, K=512
// in 16 stages of k32; 256 thr, 8 warps (4M x 2N); 2 CTAs/SM. (R8-verified)
// ---------------------------------------------------------------------------
#define TSROW 80
#define TPLANE (128*TSROW)
#define TR_STAGE (4*TPLANE)
#define TR_SMEM  (2*TR_STAGE)

__global__ __launch_bounds__(256, 2) void tri_lm(
    const uint32_t* __restrict__ AhG, const uint32_t* __restrict__ AlG,
    const uint32_t* __restrict__ BhG, const uint32_t* __restrict__ BlG,
    float* __restrict__ Ot)
{
    extern __shared__ char smraw[];
    uint32_t sb = smem_u32(smraw);
    int t = threadIdx.x, warp = t>>5, lane = t&31, g = lane>>2, tg = lane&3;
    int j0 = blockIdx.x * 128, i0 = blockIdx.y * 128, cz = blockIdx.z;
    int m0 = (warp & 3) * 32, n0 = (warp >> 2) * 64;

    size_t cb = (size_t)cz * (NN_/2);
    const char* p0 = (const char*)(AhG + cb + (size_t)i0*256);
    const char* p1 = (const char*)(AlG + cb + (size_t)i0*256);
    const char* p2 = (const char*)(BhG + cb + (size_t)j0*256);
    const char* p3 = (const char*)(BlG + cb + (size_t)j0*256);

    int lr = (t >> 1) & 127;
    int lc2 = (t & 1) * 32;
    auto load_stage = [&](int st, int slot) {
        uint32_t d = sb + slot*TR_STAGE + lr*TSROW + lc2;
        size_t go = (size_t)lr*1024 + st*64 + lc2;
        cp16s(d,                  p0 + go);
        cp16s(d + 16,             p0 + go + 16);
        cp16s(d + TPLANE,         p1 + go);
        cp16s(d + TPLANE + 16,    p1 + go + 16);
        cp16s(d + 2*TPLANE,       p2 + go);
        cp16s(d + 2*TPLANE + 16,  p2 + go + 16);
        cp16s(d + 3*TPLANE,       p3 + go);
        cp16s(d + 3*TPLANE + 16,  p3 + go + 16);
        cp_commit();
    };

    float acc[2][8][4];
    #pragma unroll
    for (int mt=0; mt<2; mt++)
        #pragma unroll
        for (int nt=0; nt<8; nt++)
            #pragma unroll
            for (int q=0; q<4; q++) acc[mt][nt][q]=0.f;

    int l16 = lane & 15;
    uint32_t coff = (uint32_t)((lane >> 4) * 16);

    load_stage(0, 0);
    load_stage(1, 1);

    #pragma unroll 1
    for (int st = 0; st < 16; st++) {
        if (st < 15) CP_WAIT(1); else CP_WAIT(0);
        __syncthreads();
        uint32_t base = sb + (st & 1)*TR_STAGE;
        #pragma unroll
        for (int kc = 0; kc < 2; kc++) {
            uint32_t kb = coff + kc*32;
            uint32_t Ah[2][4], Al[2][4];
            #pragma unroll
            for (int mt=0; mt<2; mt++) {
                uint32_t ar = (uint32_t)((m0 + mt*16 + l16) * TSROW) + kb;
                ldm_x4(Ah[mt], base + ar);
                ldm_x4(Al[mt], base + TPLANE + ar);
            }
            #pragma unroll
            for (int np=0; np<4; np++) {
                uint32_t br = (uint32_t)((n0 + np*16 + l16) * TSROW) + kb;
                uint32_t B[4], Bl_[4];
                ldm_x4(B,   base + 2*TPLANE + br);
                ldm_x4(Bl_, base + 3*TPLANE + br);
                #pragma unroll
                for (int h=0; h<2; h++) {
                    uint32_t bh[2] = {B[h], B[2+h]}, bl[2] = {Bl_[h], Bl_[2+h]};
                    int nt = np*2 + h;
                    #pragma unroll
                    for (int mt=0; mt<2; mt++)
                        MMA3T(acc[mt][nt], Ah[mt], Al[mt], bh, bl);
                }
            }
        }
        __syncthreads();
        if (st + 2 < 16) load_stage(st + 2, st & 1);
    }

    float* O = Ot + (size_t)cz*NN_;
    #pragma unroll
    for (int mt=0; mt<2; mt++) {
        int r = i0 + m0 + mt*16 + g;
        #pragma unroll
        for (int nt=0; nt<8; nt++) {
            int cl = j0 + n0 + nt*8 + 2*tg;
            *(float2*)(O + (size_t)r*N_ + cl)     = make_float2(acc[mt][nt][0], acc[mt][nt][1]);
            *(float2*)(O + (size_t)(r+8)*N_ + cl) = make_float2(acc[mt][nt][2], acc[mt][nt][3]);
        }
    }
}

// ---------------------------------------------------------------------------
// out_fused: per 128-ij tile: transpose+LN(ot) -> on planes in smem,
// GEMM vs wo planes, out = gate .* result (fp32 row-major).
// smem: OT tile fp32 [0,67584) | ON planes [67584,137216) | WO [137216,206848) | lnwb 1KB
// ---------------------------------------------------------------------------
#define OF_ON   67584
#define OF_WO   137216
#define OF_WS   206848
#define OF_SMEM 207872

__global__ __launch_bounds__(512, 1) void out_fused(
    const float* __restrict__ ot, const float* __restrict__ gate,
    const float* __restrict__ lnw, const float* __restrict__ lnb,
    const uint32_t* __restrict__ WoH, const uint32_t* __restrict__ WoL,
    float* __restrict__ out)
{
    extern __shared__ char sm[];
    uint32_t sb = smem_u32(sm);
    int t = threadIdx.x, warp = t>>5, lane = t&31, g = lane>>2, tg = lane&3;
    int l16 = lane & 15;
    uint32_t coff = (uint32_t)((lane >> 4) * 16);
    int m0 = (warp & 3) * 32, n0 = (warp >> 2) * 32;
    size_t ij0 = (size_t)blockIdx.x * 128;

    // group 1: OT tile [c=0..127][ij 0..127] fp32, stride 132
    #pragma unroll
    for (int i = 0; i < 8; i++) {
        int e = i*512 + t, c = e >> 5, c4 = e & 31;
        cp16s(sb + (uint32_t)(c*528 + c4*16),
              (const char*)(ot + (size_t)c*NN_ + ij0) + c4*16);
    }
    cp_commit();
    // group 2: WO planes
    #pragma unroll
    for (int i = 0; i < 8; i++) {
        int e = i*512 + t;
        int pl = e >> 11, r = (e >> 4) & 127, ch = e & 15;
        const uint32_t* s_ = pl ? WoL : WoH;
        cp16s(sb + OF_WO + (uint32_t)(pl*XPL + r*XROW + ch*16), s_ + (size_t)r*64 + ch*4);
    }
    cp_commit();

    if (t < 128) {
        ((float*)(sm + OF_WS))[t]       = lnw[t];
        ((float*)(sm + OF_WS))[128 + t] = lnb[t];
    }

    CP_WAIT(1); __syncthreads();   // OT ready

    // LN over c per ij -> ON planes
    {
        float* s  = (float*)sm;
        float* wv = (float*)(sm + OF_WS);
        int ij = t >> 2, q = t & 3;
        float y[32];
        float s1 = 0.f, s2 = 0.f;
        #pragma unroll
        for (int i = 0; i < 32; i++) {
            float v = s[(q*32 + i)*132 + ij];
            y[i] = v; s1 += v; s2 += v*v;
        }
        s1 += __shfl_xor_sync(~0u, s1, 1); s2 += __shfl_xor_sync(~0u, s2, 1);
        s1 += __shfl_xor_sync(~0u, s1, 2); s2 += __shfl_xor_sync(~0u, s2, 2);
        float mu  = s1 * (1.f/128.f);
        float var = s2 * (1.f/128.f) - mu*mu;
        float inv = rsqrtf(var + 1e-5f);
        uint32_t* oh = (uint32_t*)(sm + OF_ON + ij*XROW);
        uint32_t* ol = (uint32_t*)(sm + OF_ON + XPL + ij*XROW);
        #pragma unroll
        for (int j = 0; j < 16; j++) {
            int c0 = q*32 + 2*j;
            float y0 = (y[2*j]   - mu) * inv * wv[c0]   + wv[128 + c0];
            float y1 = (y[2*j+1] - mu) * inv * wv[c0+1] + wv[128 + c0 + 1];
            uint2 p = pack_split(y0, y1);
            oh[q*16 + j] = p.x;
            ol[q*16 + j] = p.y;
        }
    }
    CP_WAIT(0); __syncthreads();   // ON written + WO ready

    float acc[2][4][4];
    #pragma unroll
    for (int mt=0; mt<2; mt++)
        #pragma unroll
        for (int nt=0; nt<4; nt++)
            #pragma unroll
            for (int q=0; q<4; q++) acc[mt][nt][q]=0.f;

    gemm128(sb + OF_ON, sb + OF_WO, acc, m0, n0, l16, coff);

    #pragma unroll
    for (int mt=0; mt<2; mt++) {
        size_t rl = ij0 + m0 + mt*16 + g;
        size_t rh = rl + 8;
        #pragma unroll
        for (int nt=0; nt<4; nt++) {
            int cl = n0 + nt*8 + 2*tg;
            float2 gl = *(const float2*)(gate + rl*C_ + cl);
            float2 gh = *(const float2*)(gate + rh*C_ + cl);
            *(float2*)(out + rl*C_ + cl) =
                make_float2(gl.x * acc[mt][nt][0], gl.y * acc[mt][nt][1]);
            *(float2*)(out + rh*C_ + cl) =
                make_float2(gh.x * acc[mt][nt][2], gh.y * acc[mt][nt][3]);
        }
    }
}

// ---------------------------------------------------------------------------
extern "C" void kernel_launch(void* const* d_in, const int* in_sizes, int n_in,
                              void* d_out, int out_size)
{
    const float* z      = (const float*)d_in[0];
    const float* mask   = (const float*)d_in[1];
    const float* ln_i_w = (const float*)d_in[2];
    const float* ln_i_b = (const float*)d_in[3];
    const float* ln_o_w = (const float*)d_in[4];
    const float* ln_o_b = (const float*)d_in[5];
    const float* w_pa   = (const float*)d_in[6];
    const float* w_pb   = (const float*)d_in[7];
    const float* w_ga   = (const float*)d_in[8];
    const float* w_gb   = (const float*)d_in[9];
    const float* w_g    = (const float*)d_in[10];
    const float* w_o    = (const float*)d_in[11];
    float* out = (float*)d_out;

    uint32_t *ath, *atl, *bth, *btl, *wh, *wl;
    float *gt, *ot;
    cudaGetSymbolAddress((void**)&ath, g_ath);
    cudaGetSymbolAddress((void**)&atl, g_atl);
    cudaGetSymbolAddress((void**)&bth, g_bth);
    cudaGetSymbolAddress((void**)&btl, g_btl);
    cudaGetSymbolAddress((void**)&wh,  g_wh);
    cudaGetSymbolAddress((void**)&wl,  g_wl);
    cudaGetSymbolAddress((void**)&gt,  g_gt);
    cudaGetSymbolAddress((void**)&ot,  g_ot);

    cudaFuncSetAttribute(proj_fused, cudaFuncAttributeMaxDynamicSharedMemorySize, PJ_SMEM);
    cudaFuncSetAttribute(out_fused,  cudaFuncAttributeMaxDynamicSharedMemorySize, OF_SMEM);
    cudaFuncSetAttribute(tri_lm,     cudaFuncAttributeMaxDynamicSharedMemorySize, TR_SMEM);

    // weight plane order: ga=0, pa=1, gb=2, pb=3, g=4, o=5
    split_w_lm<<<dim3(32, 6), 256>>>(w_ga, w_pa, w_gb, w_pb, w_g, w_o, wh, wl);
    // LN(z) + 5 projections fused
    proj_fused<<<NN_/128, 512, PJ_SMEM>>>(z, mask, ln_i_w, ln_i_b, wh, wl,
                                          ath, atl, bth, btl, gt);
    // triangle einsum -> ot c-major fp32
    tri_lm<<<dim3(N_/128, N_/128, C_), 256, TR_SMEM>>>(ath, atl, bth, btl, ot);
    // transpose+LN+GEMM+gate fused
    out_fused<<<NN_/128, 512, OF_SMEM>>>(ot, gt, ln_o_w, ln_o_b,
                                         wh + 5*C_*64, wl + 5*C_*64, out);
}

// round 10
// speedup vs baseline: 1.7140x; 1.3174x over previous
#include <cuda_runtime.h>
#include <cuda_fp16.h>
#include <cstdint>

#define N_  512
#define C_  128
#define NN_ (N_*N_)

// ---------------------------------------------------------------------------
// global scratch (fp16 planes stored as uint32 = half2 of consecutive k pair)
// ---------------------------------------------------------------------------
__device__ uint32_t g_ath[(size_t)C_*(NN_/2)];  // a hi, c-major [c][(i*512+k)/2]
__device__ uint32_t g_atl[(size_t)C_*(NN_/2)];  // a lo
__device__ uint32_t g_bth[(size_t)C_*(NN_/2)];  // b hi (lo not needed: B-side)
__device__ uint32_t g_wh [6*C_*64];             // weight hi planes [which][n][k/2]
__device__ float    g_gt [(size_t)NN_*C_];      // gate fp32 row-major
__device__ float    g_ot [(size_t)C_*NN_];      // einsum out fp32, c-major

// ---------------------------------------------------------------------------
__device__ __forceinline__ float sigf(float x) { return 1.f / (1.f + __expf(-x)); }

// pack two fp32 into (hi f16x2, lo f16x2); low half = x0
__device__ __forceinline__ uint2 pack_split(float x0, float x1) {
    __half2 hh = __floats2half2_rn(x0, x1);
    float r0 = x0 - __half2float(__low2half(hh));
    float r1 = x1 - __half2float(__high2half(hh));
    __half2 ll = __floats2half2_rn(r0, r1);
    uint2 out;
    out.x = *reinterpret_cast<uint32_t*>(&hh);
    out.y = *reinterpret_cast<uint32_t*>(&ll);
    return out;
}

__device__ __forceinline__ void mma_f16(float* c, const uint32_t* a, const uint32_t* b) {
    asm volatile(
        "mma.sync.aligned.m16n8k16.row.col.f32.f16.f16.f32 "
        "{%0,%1,%2,%3},{%4,%5,%6,%7},{%8,%9},{%0,%1,%2,%3};\n"
        : "+f"(c[0]), "+f"(c[1]), "+f"(c[2]), "+f"(c[3])
        : "r"(a[0]), "r"(a[1]), "r"(a[2]), "r"(a[3]), "r"(b[0]), "r"(b[1]));
}

__device__ __forceinline__ uint32_t smem_u32(const void* p) {
    uint32_t a;
    asm("{ .reg .u64 t; cvta.to.shared.u64 t, %1; cvt.u32.u64 %0, t; }" : "=r"(a) : "l"(p));
    return a;
}
__device__ __forceinline__ void cp16s(uint32_t saddr, const void* g) {
    asm volatile("cp.async.cg.shared.global [%0], [%1], 16;\n" :: "r"(saddr), "l"(g));
}
__device__ __forceinline__ void cp_commit() { asm volatile("cp.async.commit_group;\n"); }
#define CP_WAIT(n) asm volatile("cp.async.wait_group %0;\n" :: "n"(n))

__device__ __forceinline__ void ldm_x4(uint32_t* r, uint32_t addr) {
    asm volatile("ldmatrix.sync.aligned.m8n8.x4.shared.b16 {%0,%1,%2,%3}, [%4];"
        : "=r"(r[0]), "=r"(r[1]), "=r"(r[2]), "=r"(r[3]) : "r"(addr));
}

// 2-term split MMA: acc += Ah*Bh + Al*Bh   (== (Ah+Al)*Bh, drops A*Bl ~2^-12)
#define MMA2T(acc, AH, AL, BH) do {      \
    mma_f16(acc, AH, BH);                \
    mma_f16(acc, AL, BH);                \
} while (0)

// ---------------------------------------------------------------------------
// shared 128x128x128 GEMM body (2-term fp16 split).
// X planes at xb (hi) / xb+XPL (lo); W hi plane at wb. Row stride 272B.
// warp tile 32x32, 16 warps (4M x 4N).
// ---------------------------------------------------------------------------
#define XROW 272
#define XPL  34816

__device__ __forceinline__ void gemm128(uint32_t xb, uint32_t wb, float acc[2][4][4],
                                        int m0, int n0, int l16, uint32_t coff)
{
    #pragma unroll
    for (int kc = 0; kc < 8; kc++) {
        uint32_t kb = coff + kc*32;
        uint32_t Ah[2][4], Al[2][4];
        #pragma unroll
        for (int mt = 0; mt < 2; mt++) {
            uint32_t ar = (uint32_t)((m0 + mt*16 + l16) * XROW) + kb;
            ldm_x4(Ah[mt], xb + ar);
            ldm_x4(Al[mt], xb + XPL + ar);
        }
        #pragma unroll
        for (int np = 0; np < 2; np++) {
            uint32_t br = (uint32_t)((n0 + np*16 + l16) * XROW) + kb;
            uint32_t Bh[4];
            ldm_x4(Bh, wb + br);
            #pragma unroll
            for (int h = 0; h < 2; h++) {
                uint32_t bh[2] = {Bh[h], Bh[2+h]};
                int nt = np*2 + h;
                #pragma unroll
                for (int mt = 0; mt < 2; mt++)
                    MMA2T(acc[mt][nt], Ah[mt], Al[mt], bh);
            }
        }
    }
}

// ---------------------------------------------------------------------------
// weight split -> hi plane only.  order: ga=0, pa=1, gb=2, pb=3, g=4, o=5
// ---------------------------------------------------------------------------
__global__ __launch_bounds__(256) void split_w_lm(
    const float* __restrict__ w0, const float* __restrict__ w1,
    const float* __restrict__ w2, const float* __restrict__ w3,
    const float* __restrict__ w4, const float* __restrict__ w5,
    uint32_t* __restrict__ wh)
{
    int which = blockIdx.y;
    const float* w = which==0?w0 : which==1?w1 : which==2?w2 :
                     which==3?w3 : which==4?w4 : w5;
    int e = blockIdx.x*256 + threadIdx.x;
    int n = e >> 6, kk = e & 63;
    __half2 hh = __floats2half2_rn(w[n*C_ + 2*kk], w[n*C_ + 2*kk + 1]);
    wh[which*C_*64 + e] = *reinterpret_cast<uint32_t*>(&hh);
}

// ---------------------------------------------------------------------------
// proj_fused: per 128-row tile: LN(z) in smem -> X planes, then 5 GEMMs
// smem: X planes [0,69632) | B0 [69632,104448) | B1 [104448,139264) | lnwb 1KB
// z fp32 tile is staged INTO the X region (67584B) and converted in place.
// epilogue fp32 tile spans B0+B1 [69632,137216).
// ---------------------------------------------------------------------------
#define PJ_B0   69632
#define PJ_B1   104448
#define PJ_WS   139264
#define PJ_SMEM 140288

__global__ __launch_bounds__(512, 1) void proj_fused(
    const float* __restrict__ z, const float* __restrict__ mask,
    const float* __restrict__ lnw, const float* __restrict__ lnb,
    const uint32_t* __restrict__ WH,
    uint32_t* __restrict__ aH, uint32_t* __restrict__ aL,
    uint32_t* __restrict__ bH,
    float* __restrict__ gate)
{
    extern __shared__ char sm[];
    uint32_t sb = smem_u32(sm);
    int t = threadIdx.x, warp = t>>5, lane = t&31, g = lane>>2, tg = lane&3;
    int l16 = lane & 15;
    uint32_t coff = (uint32_t)((lane >> 4) * 16);
    int m0 = (warp & 3) * 32, n0 = (warp >> 2) * 32;
    size_t row0 = (size_t)blockIdx.x * 128;

    auto loadW = [&](int which, uint32_t dst) {
        const uint32_t* srcH = WH + which*8192;
        #pragma unroll
        for (int i = 0; i < 4; i++) {
            int e = i*512 + t;               // 0..2047
            int r = e >> 4, ch = e & 15;
            cp16s(dst + (uint32_t)(r*XROW + ch*16), srcH + (size_t)r*64 + ch*4);
        }
        cp_commit();
    };

    // group1: z tile into X region as fp32 [128][132]
    {
        const char* zp = (const char*)(z + row0*C_);
        #pragma unroll
        for (int i = 0; i < 8; i++) {
            int e = i*512 + t, r = e >> 5, c4 = e & 31;
            cp16s(sb + (uint32_t)(r*528 + c4*16), zp + (size_t)r*512 + c4*16);
        }
        cp_commit();
    }
    // group2/3: preload ga, pa while z lands
    loadW(0, sb + PJ_B0);
    loadW(1, sb + PJ_B1);

    if (t < 128) {
        ((float*)(sm + PJ_WS))[t]       = lnw[t];
        ((float*)(sm + PJ_WS))[128 + t] = lnb[t];
    }

    CP_WAIT(2);
    __syncthreads();

    // LN in place: read z rows into regs, sync, write fp16 planes over same region
    {
        float* s  = (float*)sm;
        float* wv = (float*)(sm + PJ_WS);
        int r = t >> 2, q = t & 3;
        float y[32];
        float s1 = 0.f, s2 = 0.f;
        #pragma unroll
        for (int i = 0; i < 32; i++) {
            float v = s[r*132 + q*32 + i];
            y[i] = v; s1 += v; s2 += v*v;
        }
        s1 += __shfl_xor_sync(~0u, s1, 1); s2 += __shfl_xor_sync(~0u, s2, 1);
        s1 += __shfl_xor_sync(~0u, s1, 2); s2 += __shfl_xor_sync(~0u, s2, 2);
        float mu  = s1 * (1.f/128.f);
        float var = s2 * (1.f/128.f) - mu*mu;
        float inv = rsqrtf(var + 1e-5f);
        __syncthreads();                     // all reads done before overwrite
        uint32_t* xh = (uint32_t*)(sm + r*XROW);
        uint32_t* xl = (uint32_t*)(sm + XPL + r*XROW);
        #pragma unroll
        for (int j = 0; j < 16; j++) {
            int c0 = q*32 + 2*j;
            float y0 = (y[2*j]   - mu) * inv * wv[c0]   + wv[128 + c0];
            float y1 = (y[2*j+1] - mu) * inv * wv[c0+1] + wv[128 + c0 + 1];
            uint2 p = pack_split(y0, y1);
            xh[q*16 + j] = p.x;
            xl[q*16 + j] = p.y;
        }
    }
    __syncthreads();

    float acc1[2][4][4], acc2[2][4][4];
    auto zacc = [&]() {
        #pragma unroll
        for (int mt = 0; mt < 2; mt++)
            #pragma unroll
            for (int nt = 0; nt < 4; nt++)
                #pragma unroll
                for (int q = 0; q < 4; q++) { acc1[mt][nt][q] = 0.f; acc2[mt][nt][q] = 0.f; }
    };

    // epilogue: y = mask*sig(acc1)*acc2 -> c-major packed planes (tile spans B0+B1)
    auto epi_ab = [&](uint32_t* Yh, uint32_t* Yl) {
        __syncthreads();
        float* so = (float*)(sm + PJ_B0);
        #pragma unroll
        for (int mt = 0; mt < 2; mt++) {
            int rl = m0 + mt*16 + g, rh = rl + 8;
            float ml = mask[row0 + rl], mh = mask[row0 + rh];
            #pragma unroll
            for (int nt = 0; nt < 4; nt++) {
                int cl = n0 + nt*8 + 2*tg;
                so[rl*132 + cl]     = ml * sigf(acc1[mt][nt][0]) * acc2[mt][nt][0];
                so[rl*132 + cl + 1] = ml * sigf(acc1[mt][nt][1]) * acc2[mt][nt][1];
                so[rh*132 + cl]     = mh * sigf(acc1[mt][nt][2]) * acc2[mt][nt][2];
                so[rh*132 + cl + 1] = mh * sigf(acc1[mt][nt][3]) * acc2[mt][nt][3];
            }
        }
        __syncthreads();
        int c = t >> 2, p0 = (t & 3) * 16;
        size_t ub = (size_t)c * (NN_/2) + row0/2;
        #pragma unroll
        for (int p = 0; p < 16; p++) {
            int pr = p0 + p;
            uint2 pv = pack_split(so[(2*pr)*132 + c], so[(2*pr+1)*132 + c]);
            Yh[ub + pr] = pv.x;
            if (Yl) Yl[ub + pr] = pv.y;
        }
        __syncthreads();
    };

    // ---- ga,pa -> a ----
    zacc();
    CP_WAIT(1); __syncthreads();
    gemm128(sb, sb + PJ_B0, acc1, m0, n0, l16, coff);      // ga
    CP_WAIT(0); __syncthreads();
    gemm128(sb, sb + PJ_B1, acc2, m0, n0, l16, coff);      // pa
    epi_ab(aH, aL);
    // ---- gb,pb -> b ----
    loadW(2, sb + PJ_B0);
    loadW(3, sb + PJ_B1);
    zacc();
    CP_WAIT(1); __syncthreads();
    gemm128(sb, sb + PJ_B0, acc1, m0, n0, l16, coff);      // gb
    CP_WAIT(0); __syncthreads();
    gemm128(sb, sb + PJ_B1, acc2, m0, n0, l16, coff);      // pb
    epi_ab(bH, nullptr);
    // ---- wg -> gate ----
    loadW(4, sb + PJ_B0);
    zacc();
    CP_WAIT(0); __syncthreads();
    gemm128(sb, sb + PJ_B0, acc1, m0, n0, l16, coff);      // wg

    #pragma unroll
    for (int mt = 0; mt < 2; mt++) {
        size_t rl = row0 + m0 + mt*16 + g;
        size_t rh = rl + 8;
        #pragma unroll
        for (int nt = 0; nt < 4; nt++) {
            int cl = n0 + nt*8 + 2*tg;
            *(float2*)(gate + rl*C_ + cl) =
                make_float2(sigf(acc1[mt][nt][0]), sigf(acc1[mt][nt][1]));
            *(float2*)(gate + rh*C_ + cl) =
                make_float2(sigf(acc1[mt][nt][2]), sigf(acc1[mt][nt][3]));
        }
    }
}

// ---------------------------------------------------------------------------
// tri: per channel cz, Ot[i][j] = sum_k A[i,k]*B[j,k]; 128x128 tile, K=512
// in 16 stages of k32; 256 thr, 8 warps (4M x 2N); 2 CTAs/SM.
// 3 planes per stage: A hi, A lo, B hi (2-term split).
// ---------------------------------------------------------------------------
#define TSROW 80
#define TPLANE (128*TSROW)
#define TR_STAGE (3*TPLANE)          // 30720
#define TR_SMEM  (2*TR_STAGE)        // 61440

__global__ __launch_bounds__(256, 2) void tri_lm(
    const uint32_t* __restrict__ AhG, const uint32_t* __restrict__ AlG,
    const uint32_t* __restrict__ BhG,
    float* __restrict__ Ot)
{
    extern __shared__ char smraw[];
    uint32_t sb = smem_u32(smraw);
    int t = threadIdx.x, warp = t>>5, lane = t&31, g = lane>>2, tg = lane&3;
    int j0 = blockIdx.x * 128, i0 = blockIdx.y * 128, cz = blockIdx.z;
    int m0 = (warp & 3) * 32, n0 = (warp >> 2) * 64;

    size_t cb = (size_t)cz * (NN_/2);
    const char* p0 = (const char*)(AhG + cb + (size_t)i0*256);
    const char* p1 = (const char*)(AlG + cb + (size_t)i0*256);
    const char* p2 = (const char*)(BhG + cb + (size_t)j0*256);

    // loader: 3 planes x 128 rows x 4 chunks(16B) = 1536 cp16 / 256 thr = 6 each
    auto load_stage = [&](int st, int slot) {
        uint32_t base = sb + slot*TR_STAGE;
        #pragma unroll
        for (int i = 0; i < 6; i++) {
            int e = i*256 + t;                 // 0..1535
            int pl = e >> 9;
            int w_ = e & 511;
            int r = w_ >> 2, ch = (w_ & 3) * 16;
            const char* src = pl == 0 ? p0 : (pl == 1 ? p1 : p2);
            cp16s(base + (uint32_t)(pl*TPLANE + r*TSROW + ch),
                  src + (size_t)r*1024 + st*64 + ch);
        }
        cp_commit();
    };

    float acc[2][8][4];
    #pragma unroll
    for (int mt=0; mt<2; mt++)
        #pragma unroll
        for (int nt=0; nt<8; nt++)
            #pragma unroll
            for (int q=0; q<4; q++) acc[mt][nt][q]=0.f;

    int l16 = lane & 15;
    uint32_t coff = (uint32_t)((lane >> 4) * 16);

    load_stage(0, 0);
    load_stage(1, 1);

    #pragma unroll 1
    for (int st = 0; st < 16; st++) {
        if (st < 15) CP_WAIT(1); else CP_WAIT(0);
        __syncthreads();
        uint32_t base = sb + (st & 1)*TR_STAGE;
        #pragma unroll
        for (int kc = 0; kc < 2; kc++) {
            uint32_t kb = coff + kc*32;
            uint32_t Ah[2][4], Al[2][4];
            #pragma unroll
            for (int mt=0; mt<2; mt++) {
                uint32_t ar = (uint32_t)((m0 + mt*16 + l16) * TSROW) + kb;
                ldm_x4(Ah[mt], base + ar);
                ldm_x4(Al[mt], base + TPLANE + ar);
            }
            #pragma unroll
            for (int np=0; np<4; np++) {
                uint32_t br = (uint32_t)((n0 + np*16 + l16) * TSROW) + kb;
                uint32_t Bh[4];
                ldm_x4(Bh, base + 2*TPLANE + br);
                #pragma unroll
                for (int h=0; h<2; h++) {
                    uint32_t bh[2] = {Bh[h], Bh[2+h]};
                    int nt = np*2 + h;
                    #pragma unroll
                    for (int mt=0; mt<2; mt++)
                        MMA2T(acc[mt][nt], Ah[mt], Al[mt], bh);
                }
            }
        }
        __syncthreads();
        if (st + 2 < 16) load_stage(st + 2, st & 1);
    }

    float* O = Ot + (size_t)cz*NN_;
    #pragma unroll
    for (int mt=0; mt<2; mt++) {
        int r = i0 + m0 + mt*16 + g;
        #pragma unroll
        for (int nt=0; nt<8; nt++) {
            int cl = j0 + n0 + nt*8 + 2*tg;
            *(float2*)(O + (size_t)r*N_ + cl)     = make_float2(acc[mt][nt][0], acc[mt][nt][1]);
            *(float2*)(O + (size_t)(r+8)*N_ + cl) = make_float2(acc[mt][nt][2], acc[mt][nt][3]);
        }
    }
}

// ---------------------------------------------------------------------------
// out_fused: per 128-ij tile: transpose+LN(ot) -> on planes (in place over the
// ot tile), GEMM vs wo hi plane, out = gate .* result.
// smem: OT fp32 tile / ON planes [0,69632) | WO [69632,104448) | lnwb 1KB
// ---------------------------------------------------------------------------
#define OF_WO   69632
#define OF_WS   104448
#define OF_SMEM 105472

__global__ __launch_bounds__(512, 1) void out_fused(
    const float* __restrict__ ot, const float* __restrict__ gate,
    const float* __restrict__ lnw, const float* __restrict__ lnb,
    const uint32_t* __restrict__ WoH,
    float* __restrict__ out)
{
    extern __shared__ char sm[];
    uint32_t sb = smem_u32(sm);
    int t = threadIdx.x, warp = t>>5, lane = t&31, g = lane>>2, tg = lane&3;
    int l16 = lane & 15;
    uint32_t coff = (uint32_t)((lane >> 4) * 16);
    int m0 = (warp & 3) * 32, n0 = (warp >> 2) * 32;
    size_t ij0 = (size_t)blockIdx.x * 128;

    // group1: OT tile [c][ij] fp32, stride 132
    #pragma unroll
    for (int i = 0; i < 8; i++) {
        int e = i*512 + t, c = e >> 5, c4 = e & 31;
        cp16s(sb + (uint32_t)(c*528 + c4*16),
              (const char*)(ot + (size_t)c*NN_ + ij0) + c4*16);
    }
    cp_commit();
    // group2: WO hi plane
    #pragma unroll
    for (int i = 0; i < 4; i++) {
        int e = i*512 + t;
        int r = e >> 4, ch = e & 15;
        cp16s(sb + OF_WO + (uint32_t)(r*XROW + ch*16), WoH + (size_t)r*64 + ch*4);
    }
    cp_commit();

    if (t < 128) {
        ((float*)(sm + OF_WS))[t]       = lnw[t];
        ((float*)(sm + OF_WS))[128 + t] = lnb[t];
    }

    CP_WAIT(1); __syncthreads();   // OT ready

    // LN over c per ij -> ON planes (in place over OT region)
    {
        float* s  = (float*)sm;
        float* wv = (float*)(sm + OF_WS);
        int ij = t >> 2, q = t & 3;
        float y[32];
        float s1 = 0.f, s2 = 0.f;
        #pragma unroll
        for (int i = 0; i < 32; i++) {
            float v = s[(q*32 + i)*132 + ij];
            y[i] = v; s1 += v; s2 += v*v;
        }
        s1 += __shfl_xor_sync(~0u, s1, 1); s2 += __shfl_xor_sync(~0u, s2, 1);
        s1 += __shfl_xor_sync(~0u, s1, 2); s2 += __shfl_xor_sync(~0u, s2, 2);
        float mu  = s1 * (1.f/128.f);
        float var = s2 * (1.f/128.f) - mu*mu;
        float inv = rsqrtf(var + 1e-5f);
        __syncthreads();                    // all reads done before overwrite
        uint32_t* oh = (uint32_t*)(sm + ij*XROW);
        uint32_t* ol = (uint32_t*)(sm + XPL + ij*XROW);
        #pragma unroll
        for (int j = 0; j < 16; j++) {
            int c0 = q*32 + 2*j;
            float y0 = (y[2*j]   - mu) * inv * wv[c0]   + wv[128 + c0];
            float y1 = (y[2*j+1] - mu) * inv * wv[c0+1] + wv[128 + c0 + 1];
            uint2 p = pack_split(y0, y1);
            oh[q*16 + j] = p.x;
            ol[q*16 + j] = p.y;
        }
    }
    CP_WAIT(0); __syncthreads();   // ON written + WO ready

    float acc[2][4][4];
    #pragma unroll
    for (int mt=0; mt<2; mt++)
        #pragma unroll
        for (int nt=0; nt<4; nt++)
            #pragma unroll
            for (int q=0; q<4; q++) acc[mt][nt][q]=0.f;

    gemm128(sb, sb + OF_WO, acc, m0, n0, l16, coff);

    #pragma unroll
    for (int mt=0; mt<2; mt++) {
        size_t rl = ij0 + m0 + mt*16 + g;
        size_t rh = rl + 8;
        #pragma unroll
        for (int nt=0; nt<4; nt++) {
            int cl = n0 + nt*8 + 2*tg;
            float2 gl = *(const float2*)(gate + rl*C_ + cl);
            float2 gh = *(const float2*)(gate + rh*C_ + cl);
            *(float2*)(out + rl*C_ + cl) =
                make_float2(gl.x * acc[mt][nt][0], gl.y * acc[mt][nt][1]);
            *(float2*)(out + rh*C_ + cl) =
                make_float2(gh.x * acc[mt][nt][2], gh.y * acc[mt][nt][3]);
        }
    }
}

// ---------------------------------------------------------------------------
extern "C" void kernel_launch(void* const* d_in, const int* in_sizes, int n_in,
                              void* d_out, int out_size)
{
    const float* z      = (const float*)d_in[0];
    const float* mask   = (const float*)d_in[1];
    const float* ln_i_w = (const float*)d_in[2];
    const float* ln_i_b = (const float*)d_in[3];
    const float* ln_o_w = (const float*)d_in[4];
    const float* ln_o_b = (const float*)d_in[5];
    const float* w_pa   = (const float*)d_in[6];
    const float* w_pb   = (const float*)d_in[7];
    const float* w_ga   = (const float*)d_in[8];
    const float* w_gb   = (const float*)d_in[9];
    const float* w_g    = (const float*)d_in[10];
    const float* w_o    = (const float*)d_in[11];
    float* out = (float*)d_out;

    uint32_t *ath, *atl, *bth, *wh;
    float *gt, *ot;
    cudaGetSymbolAddress((void**)&ath, g_ath);
    cudaGetSymbolAddress((void**)&atl, g_atl);
    cudaGetSymbolAddress((void**)&bth, g_bth);
    cudaGetSymbolAddress((void**)&wh,  g_wh);
    cudaGetSymbolAddress((void**)&gt,  g_gt);
    cudaGetSymbolAddress((void**)&ot,  g_ot);

    cudaFuncSetAttribute(proj_fused, cudaFuncAttributeMaxDynamicSharedMemorySize, PJ_SMEM);
    cudaFuncSetAttribute(out_fused,  cudaFuncAttributeMaxDynamicSharedMemorySize, OF_SMEM);
    cudaFuncSetAttribute(tri_lm,     cudaFuncAttributeMaxDynamicSharedMemorySize, TR_SMEM);

    // weight plane order: ga=0, pa=1, gb=2, pb=3, g=4, o=5
    split_w_lm<<<dim3(32, 6), 256>>>(w_ga, w_pa, w_gb, w_pb, w_g, w_o, wh);
    // LN(z) + 5 projections fused
    proj_fused<<<NN_/128, 512, PJ_SMEM>>>(z, mask, ln_i_w, ln_i_b, wh,
                                          ath, atl, bth, gt);
    // triangle einsum -> ot c-major fp32
    tri_lm<<<dim3(N_/128, N_/128, C_), 256, TR_SMEM>>>(ath, atl, bth, ot);
    // transpose+LN+GEMM+gate fused
    out_fused<<<NN_/128, 512, OF_SMEM>>>(ot, gt, ln_o_w, ln_o_b,
                                         wh + 5*C_*64, out);
}

// round 11
// speedup vs baseline: 1.9271x; 1.1243x over previous
#include <cuda_runtime.h>
#include <cuda_fp16.h>
#include <cstdint>

#define N_  512
#define C_  128
#define NN_ (N_*N_)

// ---------------------------------------------------------------------------
// global scratch (fp16 planes stored as uint32 = half2 of consecutive k pair)
// ---------------------------------------------------------------------------
__device__ uint32_t g_ath[(size_t)C_*(NN_/2)];  // a hi, c-major [c][(i*512+k)/2]
__device__ uint32_t g_atl[(size_t)C_*(NN_/2)];  // a lo
__device__ uint32_t g_bth[(size_t)C_*(NN_/2)];  // b hi
__device__ uint32_t g_wh [6*C_*64];             // weight hi planes [which][n][k/2]
__device__ float    g_gt [(size_t)NN_*C_];      // gate fp32 row-major
__device__ float    g_ot [(size_t)C_*NN_];      // einsum out fp32, c-major

// ---------------------------------------------------------------------------
__device__ __forceinline__ float sigf(float x) { return 1.f / (1.f + __expf(-x)); }

__device__ __forceinline__ uint2 pack_split(float x0, float x1) {
    __half2 hh = __floats2half2_rn(x0, x1);
    float r0 = x0 - __half2float(__low2half(hh));
    float r1 = x1 - __half2float(__high2half(hh));
    __half2 ll = __floats2half2_rn(r0, r1);
    uint2 out;
    out.x = *reinterpret_cast<uint32_t*>(&hh);
    out.y = *reinterpret_cast<uint32_t*>(&ll);
    return out;
}

__device__ __forceinline__ void mma_f16(float* c, const uint32_t* a, const uint32_t* b) {
    asm volatile(
        "mma.sync.aligned.m16n8k16.row.col.f32.f16.f16.f32 "
        "{%0,%1,%2,%3},{%4,%5,%6,%7},{%8,%9},{%0,%1,%2,%3};\n"
        : "+f"(c[0]), "+f"(c[1]), "+f"(c[2]), "+f"(c[3])
        : "r"(a[0]), "r"(a[1]), "r"(a[2]), "r"(a[3]), "r"(b[0]), "r"(b[1]));
}

__device__ __forceinline__ uint32_t smem_u32(const void* p) {
    uint32_t a;
    asm("{ .reg .u64 t; cvta.to.shared.u64 t, %1; cvt.u32.u64 %0, t; }" : "=r"(a) : "l"(p));
    return a;
}
__device__ __forceinline__ void cp16s(uint32_t saddr, const void* g) {
    asm volatile("cp.async.cg.shared.global [%0], [%1], 16;\n" :: "r"(saddr), "l"(g));
}
__device__ __forceinline__ void cp_commit() { asm volatile("cp.async.commit_group;\n"); }
#define CP_WAIT(n) asm volatile("cp.async.wait_group %0;\n" :: "n"(n))

__device__ __forceinline__ void ldm_x4(uint32_t* r, uint32_t addr) {
    asm volatile("ldmatrix.sync.aligned.m8n8.x4.shared.b16 {%0,%1,%2,%3}, [%4];"
        : "=r"(r[0]), "=r"(r[1]), "=r"(r[2]), "=r"(r[3]) : "r"(addr));
}

#define MMA2T(acc, AH, AL, BH) do {      \
    mma_f16(acc, AH, BH);                \
    mma_f16(acc, AL, BH);                \
} while (0)

// ---------------------------------------------------------------------------
// 64xN x128 GEMM body (2-term fp16): X planes at xb (hi) / xb+XPLA (lo),
// W hi plane at wb (128 rows, stride 272B). 8 warps, warp tile 32x32 (2M x 4N).
// ---------------------------------------------------------------------------
#define XROW 272

template<int XPLA>
__device__ __forceinline__ void gemm64(uint32_t xb, uint32_t wb, float acc[2][4][4],
                                       int m0, int n0, int l16, uint32_t coff)
{
    #pragma unroll
    for (int kc = 0; kc < 8; kc++) {
        uint32_t kb = coff + kc*32;
        uint32_t Ah[2][4], Al[2][4];
        #pragma unroll
        for (int mt = 0; mt < 2; mt++) {
            uint32_t ar = (uint32_t)((m0 + mt*16 + l16) * XROW) + kb;
            ldm_x4(Ah[mt], xb + ar);
            ldm_x4(Al[mt], xb + XPLA + ar);
        }
        #pragma unroll
        for (int np = 0; np < 2; np++) {
            uint32_t br = (uint32_t)((n0 + np*16 + l16) * XROW) + kb;
            uint32_t Bh[4];
            ldm_x4(Bh, wb + br);
            #pragma unroll
            for (int h = 0; h < 2; h++) {
                uint32_t bh[2] = {Bh[h], Bh[2+h]};
                int nt = np*2 + h;
                #pragma unroll
                for (int mt = 0; mt < 2; mt++)
                    MMA2T(acc[mt][nt], Ah[mt], Al[mt], bh);
            }
        }
    }
}

// ---------------------------------------------------------------------------
// weight split -> hi planes.  order: ga=0, pa=1, gb=2, pb=3, g=4, o=5
// ---------------------------------------------------------------------------
__global__ __launch_bounds__(256) void split_w_lm(
    const float* __restrict__ w0, const float* __restrict__ w1,
    const float* __restrict__ w2, const float* __restrict__ w3,
    const float* __restrict__ w4, const float* __restrict__ w5,
    uint32_t* __restrict__ wh)
{
    int which = blockIdx.y;
    const float* w = which==0?w0 : which==1?w1 : which==2?w2 :
                     which==3?w3 : which==4?w4 : w5;
    int e = blockIdx.x*256 + threadIdx.x;
    int n = e >> 6, kk = e & 63;
    __half2 hh = __floats2half2_rn(w[n*C_ + 2*kk], w[n*C_ + 2*kk + 1]);
    wh[which*C_*64 + e] = *reinterpret_cast<uint32_t*>(&hh);
}

// ---------------------------------------------------------------------------
// proj_fused: 64-row tile, 256 thr, 2 CTAs/SM.
// smem: X planes [0,34816) | B0 [34816,69632) | B1 [69632,104448) | lnwb 1KB
// ---------------------------------------------------------------------------
#define PJ_B0   34816
#define PJ_B1   69632
#define PJ_WS   104448
#define PJ_SMEM 105472
#define XPL64   17408

__global__ __launch_bounds__(256, 2) void proj_fused(
    const float* __restrict__ z, const float* __restrict__ mask,
    const float* __restrict__ lnw, const float* __restrict__ lnb,
    const uint32_t* __restrict__ WH,
    uint32_t* __restrict__ aH, uint32_t* __restrict__ aL,
    uint32_t* __restrict__ bH,
    float* __restrict__ gate)
{
    extern __shared__ char sm[];
    uint32_t sb = smem_u32(sm);
    int t = threadIdx.x, warp = t>>5, lane = t&31, g = lane>>2, tg = lane&3;
    int l16 = lane & 15;
    uint32_t coff = (uint32_t)((lane >> 4) * 16);
    int m0 = (warp & 1) * 32, n0 = (warp >> 1) * 32;
    size_t row0 = (size_t)blockIdx.x * 64;

    auto loadW = [&](int which, uint32_t dst) {
        const uint32_t* srcH = WH + which*8192;
        #pragma unroll
        for (int i = 0; i < 8; i++) {
            int e = i*256 + t;               // 0..2047
            int r = e >> 4, ch = e & 15;
            cp16s(dst + (uint32_t)(r*XROW + ch*16), srcH + (size_t)r*64 + ch*4);
        }
        cp_commit();
    };

    // group1: z tile into X region as fp32 [64][132]
    {
        const char* zp = (const char*)(z + row0*C_);
        #pragma unroll
        for (int i = 0; i < 8; i++) {
            int e = i*256 + t, r = e >> 5, c4 = e & 31;
            cp16s(sb + (uint32_t)(r*528 + c4*16), zp + (size_t)r*512 + c4*16);
        }
        cp_commit();
    }
    loadW(0, sb + PJ_B0);   // ga
    loadW(1, sb + PJ_B1);   // pa

    if (t < 128) {
        ((float*)(sm + PJ_WS))[t]       = lnw[t];
        ((float*)(sm + PJ_WS))[128 + t] = lnb[t];
    }

    CP_WAIT(2);
    __syncthreads();

    // LN in place over X region
    {
        float* s  = (float*)sm;
        float* wv = (float*)(sm + PJ_WS);
        int r = t >> 2, q = t & 3;
        float y[32];
        float s1 = 0.f, s2 = 0.f;
        #pragma unroll
        for (int i = 0; i < 32; i++) {
            float v = s[r*132 + q*32 + i];
            y[i] = v; s1 += v; s2 += v*v;
        }
        s1 += __shfl_xor_sync(~0u, s1, 1); s2 += __shfl_xor_sync(~0u, s2, 1);
        s1 += __shfl_xor_sync(~0u, s1, 2); s2 += __shfl_xor_sync(~0u, s2, 2);
        float mu  = s1 * (1.f/128.f);
        float var = s2 * (1.f/128.f) - mu*mu;
        float inv = rsqrtf(var + 1e-5f);
        __syncthreads();
        uint32_t* xh = (uint32_t*)(sm + r*XROW);
        uint32_t* xl = (uint32_t*)(sm + XPL64 + r*XROW);
        #pragma unroll
        for (int j = 0; j < 16; j++) {
            int c0 = q*32 + 2*j;
            float y0 = (y[2*j]   - mu) * inv * wv[c0]   + wv[128 + c0];
            float y1 = (y[2*j+1] - mu) * inv * wv[c0+1] + wv[128 + c0 + 1];
            uint2 p = pack_split(y0, y1);
            xh[q*16 + j] = p.x;
            xl[q*16 + j] = p.y;
        }
    }
    __syncthreads();

    float acc1[2][4][4], acc2[2][4][4];
    auto zacc = [&]() {
        #pragma unroll
        for (int mt = 0; mt < 2; mt++)
            #pragma unroll
            for (int nt = 0; nt < 4; nt++)
                #pragma unroll
                for (int q = 0; q < 4; q++) { acc1[mt][nt][q] = 0.f; acc2[mt][nt][q] = 0.f; }
    };

    // epilogue: y = mask*sig(acc1)*acc2 -> c-major packed planes (fp32 tile in B0)
    auto epi_ab = [&](uint32_t* Yh, uint32_t* Yl) {
        __syncthreads();
        float* so = (float*)(sm + PJ_B0);
        #pragma unroll
        for (int mt = 0; mt < 2; mt++) {
            int rl = m0 + mt*16 + g, rh = rl + 8;
            float ml = mask[row0 + rl], mh = mask[row0 + rh];
            #pragma unroll
            for (int nt = 0; nt < 4; nt++) {
                int cl = n0 + nt*8 + 2*tg;
                so[rl*132 + cl]     = ml * sigf(acc1[mt][nt][0]) * acc2[mt][nt][0];
                so[rl*132 + cl + 1] = ml * sigf(acc1[mt][nt][1]) * acc2[mt][nt][1];
                so[rh*132 + cl]     = mh * sigf(acc1[mt][nt][2]) * acc2[mt][nt][2];
                so[rh*132 + cl + 1] = mh * sigf(acc1[mt][nt][3]) * acc2[mt][nt][3];
            }
        }
        __syncthreads();
        int c = t >> 1, p0 = (t & 1) * 16;
        size_t ub = (size_t)c * (NN_/2) + row0/2;
        #pragma unroll
        for (int p = 0; p < 16; p++) {
            int pr = p0 + p;
            uint2 pv = pack_split(so[(2*pr)*132 + c], so[(2*pr+1)*132 + c]);
            Yh[ub + pr] = pv.x;
            if (Yl) Yl[ub + pr] = pv.y;
        }
        __syncthreads();
    };

    // ---- ga,pa -> a ----
    zacc();
    CP_WAIT(1); __syncthreads();
    gemm64<XPL64>(sb, sb + PJ_B0, acc1, m0, n0, l16, coff);      // ga
    CP_WAIT(0); __syncthreads();
    gemm64<XPL64>(sb, sb + PJ_B1, acc2, m0, n0, l16, coff);      // pa
    __syncthreads();
    loadW(2, sb + PJ_B1);          // gb (pa consumed)
    epi_ab(aH, aL);                // fp32 tile in B0 (ga consumed)
    loadW(3, sb + PJ_B0);          // pb (B0 free after epi)
    // ---- gb,pb -> b ----
    zacc();
    CP_WAIT(1); __syncthreads();
    gemm64<XPL64>(sb, sb + PJ_B1, acc1, m0, n0, l16, coff);      // gb
    CP_WAIT(0); __syncthreads();
    gemm64<XPL64>(sb, sb + PJ_B0, acc2, m0, n0, l16, coff);      // pb
    __syncthreads();
    loadW(4, sb + PJ_B1);          // wg
    epi_ab(bH, nullptr);           // fp32 tile in B0 (pb consumed)
    // ---- wg -> gate ----
    zacc();
    CP_WAIT(0); __syncthreads();
    gemm64<XPL64>(sb, sb + PJ_B1, acc1, m0, n0, l16, coff);      // wg

    #pragma unroll
    for (int mt = 0; mt < 2; mt++) {
        size_t rl = row0 + m0 + mt*16 + g;
        size_t rh = rl + 8;
        #pragma unroll
        for (int nt = 0; nt < 4; nt++) {
            int cl = n0 + nt*8 + 2*tg;
            *(float2*)(gate + rl*C_ + cl) =
                make_float2(sigf(acc1[mt][nt][0]), sigf(acc1[mt][nt][1]));
            *(float2*)(gate + rh*C_ + cl) =
                make_float2(sigf(acc1[mt][nt][2]), sigf(acc1[mt][nt][3]));
        }
    }
}

// ---------------------------------------------------------------------------
// tri: unchanged from R10 (256 thr, 2 CTAs/SM, verified).
// ---------------------------------------------------------------------------
#define TSROW 80
#define TPLANE (128*TSROW)
#define TR_STAGE (3*TPLANE)
#define TR_SMEM  (2*TR_STAGE)

__global__ __launch_bounds__(256, 2) void tri_lm(
    const uint32_t* __restrict__ AhG, const uint32_t* __restrict__ AlG,
    const uint32_t* __restrict__ BhG,
    float* __restrict__ Ot)
{
    extern __shared__ char smraw[];
    uint32_t sb = smem_u32(smraw);
    int t = threadIdx.x, warp = t>>5, lane = t&31, g = lane>>2, tg = lane&3;
    int j0 = blockIdx.x * 128, i0 = blockIdx.y * 128, cz = blockIdx.z;
    int m0 = (warp & 3) * 32, n0 = (warp >> 2) * 64;

    size_t cb = (size_t)cz * (NN_/2);
    const char* p0 = (const char*)(AhG + cb + (size_t)i0*256);
    const char* p1 = (const char*)(AlG + cb + (size_t)i0*256);
    const char* p2 = (const char*)(BhG + cb + (size_t)j0*256);

    auto load_stage = [&](int st, int slot) {
        uint32_t base = sb + slot*TR_STAGE;
        #pragma unroll
        for (int i = 0; i < 6; i++) {
            int e = i*256 + t;
            int pl = e >> 9;
            int w_ = e & 511;
            int r = w_ >> 2, ch = (w_ & 3) * 16;
            const char* src = pl == 0 ? p0 : (pl == 1 ? p1 : p2);
            cp16s(base + (uint32_t)(pl*TPLANE + r*TSROW + ch),
                  src + (size_t)r*1024 + st*64 + ch);
        }
        cp_commit();
    };

    float acc[2][8][4];
    #pragma unroll
    for (int mt=0; mt<2; mt++)
        #pragma unroll
        for (int nt=0; nt<8; nt++)
            #pragma unroll
            for (int q=0; q<4; q++) acc[mt][nt][q]=0.f;

    int l16 = lane & 15;
    uint32_t coff = (uint32_t)((lane >> 4) * 16);

    load_stage(0, 0);
    load_stage(1, 1);

    #pragma unroll 1
    for (int st = 0; st < 16; st++) {
        if (st < 15) CP_WAIT(1); else CP_WAIT(0);
        __syncthreads();
        uint32_t base = sb + (st & 1)*TR_STAGE;
        #pragma unroll
        for (int kc = 0; kc < 2; kc++) {
            uint32_t kb = coff + kc*32;
            uint32_t Ah[2][4], Al[2][4];
            #pragma unroll
            for (int mt=0; mt<2; mt++) {
                uint32_t ar = (uint32_t)((m0 + mt*16 + l16) * TSROW) + kb;
                ldm_x4(Ah[mt], base + ar);
                ldm_x4(Al[mt], base + TPLANE + ar);
            }
            #pragma unroll
            for (int np=0; np<4; np++) {
                uint32_t br = (uint32_t)((n0 + np*16 + l16) * TSROW) + kb;
                uint32_t Bh[4];
                ldm_x4(Bh, base + 2*TPLANE + br);
                #pragma unroll
                for (int h=0; h<2; h++) {
                    uint32_t bh[2] = {Bh[h], Bh[2+h]};
                    int nt = np*2 + h;
                    #pragma unroll
                    for (int mt=0; mt<2; mt++)
                        MMA2T(acc[mt][nt], Ah[mt], Al[mt], bh);
                }
            }
        }
        __syncthreads();
        if (st + 2 < 16) load_stage(st + 2, st & 1);
    }

    float* O = Ot + (size_t)cz*NN_;
    #pragma unroll
    for (int mt=0; mt<2; mt++) {
        int r = i0 + m0 + mt*16 + g;
        #pragma unroll
        for (int nt=0; nt<8; nt++) {
            int cl = j0 + n0 + nt*8 + 2*tg;
            *(float2*)(O + (size_t)r*N_ + cl)     = make_float2(acc[mt][nt][0], acc[mt][nt][1]);
            *(float2*)(O + (size_t)(r+8)*N_ + cl) = make_float2(acc[mt][nt][2], acc[mt][nt][3]);
        }
    }
}

// ---------------------------------------------------------------------------
// out_fused: 64-ij tile, 256 thr, 2 CTAs/SM.
// smem: OT/ON [0,34816) | WO [34816,69632) | lnwb 1KB
// ---------------------------------------------------------------------------
#define OF_WO   34816
#define OF_WS   69632
#define OF_SMEM 70656

__global__ __launch_bounds__(256, 2) void out_fused(
    const float* __restrict__ ot, const float* __restrict__ gate,
    const float* __restrict__ lnw, const float* __restrict__ lnb,
    const uint32_t* __restrict__ WoH,
    float* __restrict__ out)
{
    extern __shared__ char sm[];
    uint32_t sb = smem_u32(sm);
    int t = threadIdx.x, warp = t>>5, lane = t&31, g = lane>>2, tg = lane&3;
    int l16 = lane & 15;
    uint32_t coff = (uint32_t)((lane >> 4) * 16);
    int m0 = (warp & 1) * 32, n0 = (warp >> 1) * 32;
    size_t ij0 = (size_t)blockIdx.x * 64;

    // group1: OT tile [c=128][ij=64] fp32, stride 272B (68 floats)
    #pragma unroll
    for (int i = 0; i < 8; i++) {
        int e = i*256 + t, c = e >> 4, ch = e & 15;
        cp16s(sb + (uint32_t)(c*XROW + ch*16),
              (const char*)(ot + (size_t)c*NN_ + ij0) + ch*16);
    }
    cp_commit();
    // group2: WO hi plane (128 rows)
    #pragma unroll
    for (int i = 0; i < 8; i++) {
        int e = i*256 + t;
        int r = e >> 4, ch = e & 15;
        cp16s(sb + OF_WO + (uint32_t)(r*XROW + ch*16), WoH + (size_t)r*64 + ch*4);
    }
    cp_commit();

    if (t < 128) {
        ((float*)(sm + OF_WS))[t]       = lnw[t];
        ((float*)(sm + OF_WS))[128 + t] = lnb[t];
    }

    CP_WAIT(1); __syncthreads();   // OT ready

    // LN over c per ij -> ON planes (in place over OT region)
    {
        float* s  = (float*)sm;
        float* wv = (float*)(sm + OF_WS);
        int ij = t >> 2, q = t & 3;
        float y[32];
        float s1 = 0.f, s2 = 0.f;
        #pragma unroll
        for (int i = 0; i < 32; i++) {
            float v = s[(q*32 + i)*68 + ij];
            y[i] = v; s1 += v; s2 += v*v;
        }
        s1 += __shfl_xor_sync(~0u, s1, 1); s2 += __shfl_xor_sync(~0u, s2, 1);
        s1 += __shfl_xor_sync(~0u, s1, 2); s2 += __shfl_xor_sync(~0u, s2, 2);
        float mu  = s1 * (1.f/128.f);
        float var = s2 * (1.f/128.f) - mu*mu;
        float inv = rsqrtf(var + 1e-5f);
        __syncthreads();
        uint32_t* oh = (uint32_t*)(sm + ij*XROW);
        uint32_t* ol = (uint32_t*)(sm + XPL64 + ij*XROW);
        #pragma unroll
        for (int j = 0; j < 16; j++) {
            int c0 = q*32 + 2*j;
            float y0 = (y[2*j]   - mu) * inv * wv[c0]   + wv[128 + c0];
            float y1 = (y[2*j+1] - mu) * inv * wv[c0+1] + wv[128 + c0 + 1];
            uint2 p = pack_split(y0, y1);
            oh[q*16 + j] = p.x;
            ol[q*16 + j] = p.y;
        }
    }
    CP_WAIT(0); __syncthreads();   // ON written + WO ready

    float acc[2][4][4];
    #pragma unroll
    for (int mt=0; mt<2; mt++)
        #pragma unroll
        for (int nt=0; nt<4; nt++)
            #pragma unroll
            for (int q=0; q<4; q++) acc[mt][nt][q]=0.f;

    gemm64<XPL64>(sb, sb + OF_WO, acc, m0, n0, l16, coff);

    #pragma unroll
    for (int mt=0; mt<2; mt++) {
        size_t rl = ij0 + m0 + mt*16 + g;
        size_t rh = rl + 8;
        #pragma unroll
        for (int nt=0; nt<4; nt++) {
            int cl = n0 + nt*8 + 2*tg;
            float2 gl = *(const float2*)(gate + rl*C_ + cl);
            float2 gh = *(const float2*)(gate + rh*C_ + cl);
            *(float2*)(out + rl*C_ + cl) =
                make_float2(gl.x * acc[mt][nt][0], gl.y * acc[mt][nt][1]);
            *(float2*)(out + rh*C_ + cl) =
                make_float2(gh.x * acc[mt][nt][2], gh.y * acc[mt][nt][3]);
        }
    }
}

// ---------------------------------------------------------------------------
extern "C" void kernel_launch(void* const* d_in, const int* in_sizes, int n_in,
                              void* d_out, int out_size)
{
    const float* z      = (const float*)d_in[0];
    const float* mask   = (const float*)d_in[1];
    const float* ln_i_w = (const float*)d_in[2];
    const float* ln_i_b = (const float*)d_in[3];
    const float* ln_o_w = (const float*)d_in[4];
    const float* ln_o_b = (const float*)d_in[5];
    const float* w_pa   = (const float*)d_in[6];
    const float* w_pb   = (const float*)d_in[7];
    const float* w_ga   = (const float*)d_in[8];
    const float* w_gb   = (const float*)d_in[9];
    const float* w_g    = (const float*)d_in[10];
    const float* w_o    = (const float*)d_in[11];
    float* out = (float*)d_out;

    uint32_t *ath, *atl, *bth, *wh;
    float *gt, *ot;
    cudaGetSymbolAddress((void**)&ath, g_ath);
    cudaGetSymbolAddress((void**)&atl, g_atl);
    cudaGetSymbolAddress((void**)&bth, g_bth);
    cudaGetSymbolAddress((void**)&wh,  g_wh);
    cudaGetSymbolAddress((void**)&gt,  g_gt);
    cudaGetSymbolAddress((void**)&ot,  g_ot);

    cudaFuncSetAttribute(proj_fused, cudaFuncAttributeMaxDynamicSharedMemorySize, PJ_SMEM);
    cudaFuncSetAttribute(out_fused,  cudaFuncAttributeMaxDynamicSharedMemorySize, OF_SMEM);
    cudaFuncSetAttribute(tri_lm,     cudaFuncAttributeMaxDynamicSharedMemorySize, TR_SMEM);

    // weight plane order: ga=0, pa=1, gb=2, pb=3, g=4, o=5
    split_w_lm<<<dim3(32, 6), 256>>>(w_ga, w_pa, w_gb, w_pb, w_g, w_o, wh);
    // LN(z) + 5 projections fused (64-row tiles, 2 CTAs/SM)
    proj_fused<<<NN_/64, 256, PJ_SMEM>>>(z, mask, ln_i_w, ln_i_b, wh,
                                         ath, atl, bth, gt);
    // triangle einsum -> ot c-major fp32
    tri_lm<<<dim3(N_/128, N_/128, C_), 256, TR_SMEM>>>(ath, atl, bth, ot);
    // transpose+LN+GEMM+gate fused (64-ij tiles, 2 CTAs/SM)
    out_fused<<<NN_/64, 256, OF_SMEM>>>(ot, gt, ln_o_w, ln_o_b,
                                        wh + 5*C_*64, out);
}

// round 12
// speedup vs baseline: 1.9777x; 1.0263x over previous
#include <cuda_runtime.h>
#include <cuda_fp16.h>
#include <cstdint>

#define N_  512
#define C_  128
#define NN_ (N_*N_)

// ---------------------------------------------------------------------------
// global scratch (fp16 planes stored as uint32 = half2 of consecutive k pair)
// ---------------------------------------------------------------------------
__device__ uint32_t g_ath[(size_t)C_*(NN_/2)];  // a hi, c-major [c][(i*512+k)/2]
__device__ uint32_t g_atl[(size_t)C_*(NN_/2)];  // a lo
__device__ uint32_t g_bth[(size_t)C_*(NN_/2)];  // b hi
__device__ uint32_t g_wh [6*C_*64];             // weight hi planes [which][n][k/2]
__device__ uint32_t g_gt [(size_t)NN_*64];      // gate fp16 half2 [row][c/2]
__device__ uint32_t g_ot [(size_t)C_*(NN_/2)];  // einsum out fp16 half2, c-major [c][ij/2]

// ---------------------------------------------------------------------------
__device__ __forceinline__ float sigf(float x) { return 1.f / (1.f + __expf(-x)); }

__device__ __forceinline__ uint2 pack_split(float x0, float x1) {
    __half2 hh = __floats2half2_rn(x0, x1);
    float r0 = x0 - __half2float(__low2half(hh));
    float r1 = x1 - __half2float(__high2half(hh));
    __half2 ll = __floats2half2_rn(r0, r1);
    uint2 out;
    out.x = *reinterpret_cast<uint32_t*>(&hh);
    out.y = *reinterpret_cast<uint32_t*>(&ll);
    return out;
}
__device__ __forceinline__ uint32_t pack_h2(float x0, float x1) {
    __half2 hh = __floats2half2_rn(x0, x1);
    return *reinterpret_cast<uint32_t*>(&hh);
}

__device__ __forceinline__ void mma_f16(float* c, const uint32_t* a, const uint32_t* b) {
    asm volatile(
        "mma.sync.aligned.m16n8k16.row.col.f32.f16.f16.f32 "
        "{%0,%1,%2,%3},{%4,%5,%6,%7},{%8,%9},{%0,%1,%2,%3};\n"
        : "+f"(c[0]), "+f"(c[1]), "+f"(c[2]), "+f"(c[3])
        : "r"(a[0]), "r"(a[1]), "r"(a[2]), "r"(a[3]), "r"(b[0]), "r"(b[1]));
}

__device__ __forceinline__ uint32_t smem_u32(const void* p) {
    uint32_t a;
    asm("{ .reg .u64 t; cvta.to.shared.u64 t, %1; cvt.u32.u64 %0, t; }" : "=r"(a) : "l"(p));
    return a;
}
__device__ __forceinline__ void cp16s(uint32_t saddr, const void* g) {
    asm volatile("cp.async.cg.shared.global [%0], [%1], 16;\n" :: "r"(saddr), "l"(g));
}
__device__ __forceinline__ void cp_commit() { asm volatile("cp.async.commit_group;\n"); }
#define CP_WAIT(n) asm volatile("cp.async.wait_group %0;\n" :: "n"(n))

__device__ __forceinline__ void ldm_x4(uint32_t* r, uint32_t addr) {
    asm volatile("ldmatrix.sync.aligned.m8n8.x4.shared.b16 {%0,%1,%2,%3}, [%4];"
        : "=r"(r[0]), "=r"(r[1]), "=r"(r[2]), "=r"(r[3]) : "r"(addr));
}

#define MMA2T(acc, AH, AL, BH) do {      \
    mma_f16(acc, AH, BH);                \
    mma_f16(acc, AL, BH);                \
} while (0)

// ---------------------------------------------------------------------------
// 64xN x128 GEMM body (2-term fp16): X planes at xb (hi) / xb+XPLA (lo),
// W hi plane at wb (128 rows, stride 272B). 8 warps, warp tile 32x32 (2M x 4N).
// ---------------------------------------------------------------------------
#define XROW 272
#define XPL64 17408

template<int XPLA>
__device__ __forceinline__ void gemm64(uint32_t xb, uint32_t wb, float acc[2][4][4],
                                       int m0, int n0, int l16, uint32_t coff)
{
    #pragma unroll
    for (int kc = 0; kc < 8; kc++) {
        uint32_t kb = coff + kc*32;
        uint32_t Ah[2][4], Al[2][4];
        #pragma unroll
        for (int mt = 0; mt < 2; mt++) {
            uint32_t ar = (uint32_t)((m0 + mt*16 + l16) * XROW) + kb;
            ldm_x4(Ah[mt], xb + ar);
            ldm_x4(Al[mt], xb + XPLA + ar);
        }
        #pragma unroll
        for (int np = 0; np < 2; np++) {
            uint32_t br = (uint32_t)((n0 + np*16 + l16) * XROW) + kb;
            uint32_t Bh[4];
            ldm_x4(Bh, wb + br);
            #pragma unroll
            for (int h = 0; h < 2; h++) {
                uint32_t bh[2] = {Bh[h], Bh[2+h]};
                int nt = np*2 + h;
                #pragma unroll
                for (int mt = 0; mt < 2; mt++)
                    MMA2T(acc[mt][nt], Ah[mt], Al[mt], bh);
            }
        }
    }
}

// ---------------------------------------------------------------------------
// weight split -> hi planes.  order: ga=0, pa=1, gb=2, pb=3, g=4, o=5
// ---------------------------------------------------------------------------
__global__ __launch_bounds__(256) void split_w_lm(
    const float* __restrict__ w0, const float* __restrict__ w1,
    const float* __restrict__ w2, const float* __restrict__ w3,
    const float* __restrict__ w4, const float* __restrict__ w5,
    uint32_t* __restrict__ wh)
{
    int which = blockIdx.y;
    const float* w = which==0?w0 : which==1?w1 : which==2?w2 :
                     which==3?w3 : which==4?w4 : w5;
    int e = blockIdx.x*256 + threadIdx.x;
    int n = e >> 6, kk = e & 63;
    wh[which*C_*64 + e] = pack_h2(w[n*C_ + 2*kk], w[n*C_ + 2*kk + 1]);
}

// ---------------------------------------------------------------------------
// proj_fused: 64-row tile, 256 thr, 2 CTAs/SM.
// smem: X planes [0,34816) | B0 [34816,69632) | B1 [69632,104448) | lnwb 1KB
// ---------------------------------------------------------------------------
#define PJ_B0   34816
#define PJ_B1   69632
#define PJ_WS   104448
#define PJ_SMEM 105472

__global__ __launch_bounds__(256, 2) void proj_fused(
    const float* __restrict__ z, const float* __restrict__ mask,
    const float* __restrict__ lnw, const float* __restrict__ lnb,
    const uint32_t* __restrict__ WH,
    uint32_t* __restrict__ aH, uint32_t* __restrict__ aL,
    uint32_t* __restrict__ bH,
    uint32_t* __restrict__ gate)
{
    extern __shared__ char sm[];
    uint32_t sb = smem_u32(sm);
    int t = threadIdx.x, warp = t>>5, lane = t&31, g = lane>>2, tg = lane&3;
    int l16 = lane & 15;
    uint32_t coff = (uint32_t)((lane >> 4) * 16);
    int m0 = (warp & 1) * 32, n0 = (warp >> 1) * 32;
    size_t row0 = (size_t)blockIdx.x * 64;

    auto loadW = [&](int which, uint32_t dst) {
        const uint32_t* srcH = WH + which*8192;
        #pragma unroll
        for (int i = 0; i < 8; i++) {
            int e = i*256 + t;
            int r = e >> 4, ch = e & 15;
            cp16s(dst + (uint32_t)(r*XROW + ch*16), srcH + (size_t)r*64 + ch*4);
        }
        cp_commit();
    };

    // group1: z tile into X region as fp32 [64][132]
    {
        const char* zp = (const char*)(z + row0*C_);
        #pragma unroll
        for (int i = 0; i < 8; i++) {
            int e = i*256 + t, r = e >> 5, c4 = e & 31;
            cp16s(sb + (uint32_t)(r*528 + c4*16), zp + (size_t)r*512 + c4*16);
        }
        cp_commit();
    }
    loadW(0, sb + PJ_B0);   // ga
    loadW(1, sb + PJ_B1);   // pa

    if (t < 128) {
        ((float*)(sm + PJ_WS))[t]       = lnw[t];
        ((float*)(sm + PJ_WS))[128 + t] = lnb[t];
    }

    CP_WAIT(2);
    __syncthreads();

    // LN in place over X region
    {
        float* s  = (float*)sm;
        float* wv = (float*)(sm + PJ_WS);
        int r = t >> 2, q = t & 3;
        float y[32];
        float s1 = 0.f, s2 = 0.f;
        #pragma unroll
        for (int i = 0; i < 32; i++) {
            float v = s[r*132 + q*32 + i];
            y[i] = v; s1 += v; s2 += v*v;
        }
        s1 += __shfl_xor_sync(~0u, s1, 1); s2 += __shfl_xor_sync(~0u, s2, 1);
        s1 += __shfl_xor_sync(~0u, s1, 2); s2 += __shfl_xor_sync(~0u, s2, 2);
        float mu  = s1 * (1.f/128.f);
        float var = s2 * (1.f/128.f) - mu*mu;
        float inv = rsqrtf(var + 1e-5f);
        __syncthreads();
        uint32_t* xh = (uint32_t*)(sm + r*XROW);
        uint32_t* xl = (uint32_t*)(sm + XPL64 + r*XROW);
        #pragma unroll
        for (int j = 0; j < 16; j++) {
            int c0 = q*32 + 2*j;
            float y0 = (y[2*j]   - mu) * inv * wv[c0]   + wv[128 + c0];
            float y1 = (y[2*j+1] - mu) * inv * wv[c0+1] + wv[128 + c0 + 1];
            uint2 p = pack_split(y0, y1);
            xh[q*16 + j] = p.x;
            xl[q*16 + j] = p.y;
        }
    }
    __syncthreads();

    float acc1[2][4][4], acc2[2][4][4];
    auto zacc = [&]() {
        #pragma unroll
        for (int mt = 0; mt < 2; mt++)
            #pragma unroll
            for (int nt = 0; nt < 4; nt++)
                #pragma unroll
                for (int q = 0; q < 4; q++) { acc1[mt][nt][q] = 0.f; acc2[mt][nt][q] = 0.f; }
    };

    auto epi_ab = [&](uint32_t* Yh, uint32_t* Yl) {
        __syncthreads();
        float* so = (float*)(sm + PJ_B0);
        #pragma unroll
        for (int mt = 0; mt < 2; mt++) {
            int rl = m0 + mt*16 + g, rh = rl + 8;
            float ml = mask[row0 + rl], mh = mask[row0 + rh];
            #pragma unroll
            for (int nt = 0; nt < 4; nt++) {
                int cl = n0 + nt*8 + 2*tg;
                so[rl*132 + cl]     = ml * sigf(acc1[mt][nt][0]) * acc2[mt][nt][0];
                so[rl*132 + cl + 1] = ml * sigf(acc1[mt][nt][1]) * acc2[mt][nt][1];
                so[rh*132 + cl]     = mh * sigf(acc1[mt][nt][2]) * acc2[mt][nt][2];
                so[rh*132 + cl + 1] = mh * sigf(acc1[mt][nt][3]) * acc2[mt][nt][3];
            }
        }
        __syncthreads();
        int c = t >> 1, p0 = (t & 1) * 16;
        size_t ub = (size_t)c * (NN_/2) + row0/2;
        #pragma unroll
        for (int p = 0; p < 16; p++) {
            int pr = p0 + p;
            uint2 pv = pack_split(so[(2*pr)*132 + c], so[(2*pr+1)*132 + c]);
            Yh[ub + pr] = pv.x;
            if (Yl) Yl[ub + pr] = pv.y;
        }
        __syncthreads();
    };

    // ---- ga,pa -> a ----
    zacc();
    CP_WAIT(1); __syncthreads();
    gemm64<XPL64>(sb, sb + PJ_B0, acc1, m0, n0, l16, coff);      // ga
    CP_WAIT(0); __syncthreads();
    gemm64<XPL64>(sb, sb + PJ_B1, acc2, m0, n0, l16, coff);      // pa
    __syncthreads();
    loadW(2, sb + PJ_B1);          // gb
    epi_ab(aH, aL);
    loadW(3, sb + PJ_B0);          // pb
    // ---- gb,pb -> b ----
    zacc();
    CP_WAIT(1); __syncthreads();
    gemm64<XPL64>(sb, sb + PJ_B1, acc1, m0, n0, l16, coff);      // gb
    CP_WAIT(0); __syncthreads();
    gemm64<XPL64>(sb, sb + PJ_B0, acc2, m0, n0, l16, coff);      // pb
    __syncthreads();
    loadW(4, sb + PJ_B1);          // wg
    epi_ab(bH, nullptr);
    // ---- wg -> gate (fp16 packed) ----
    zacc();
    CP_WAIT(0); __syncthreads();
    gemm64<XPL64>(sb, sb + PJ_B1, acc1, m0, n0, l16, coff);      // wg

    #pragma unroll
    for (int mt = 0; mt < 2; mt++) {
        size_t rl = row0 + m0 + mt*16 + g;
        size_t rh = rl + 8;
        #pragma unroll
        for (int nt = 0; nt < 4; nt++) {
            int cl = n0 + nt*8 + 2*tg;
            gate[rl*64 + cl/2] = pack_h2(sigf(acc1[mt][nt][0]), sigf(acc1[mt][nt][1]));
            gate[rh*64 + cl/2] = pack_h2(sigf(acc1[mt][nt][2]), sigf(acc1[mt][nt][3]));
        }
    }
}

// ---------------------------------------------------------------------------
// tri: per channel cz, 128x128 tile, K=512 in 16 stages; 2 CTAs/SM.
// output packed fp16 half2 (pairs along j).
// ---------------------------------------------------------------------------
#define TSROW 80
#define TPLANE (128*TSROW)
#define TR_STAGE (3*TPLANE)
#define TR_SMEM  (2*TR_STAGE)

__global__ __launch_bounds__(256, 2) void tri_lm(
    const uint32_t* __restrict__ AhG, const uint32_t* __restrict__ AlG,
    const uint32_t* __restrict__ BhG,
    uint32_t* __restrict__ Ot)
{
    extern __shared__ char smraw[];
    uint32_t sb = smem_u32(smraw);
    int t = threadIdx.x, warp = t>>5, lane = t&31, g = lane>>2, tg = lane&3;
    int j0 = blockIdx.x * 128, i0 = blockIdx.y * 128, cz = blockIdx.z;
    int m0 = (warp & 3) * 32, n0 = (warp >> 2) * 64;

    size_t cb = (size_t)cz * (NN_/2);
    const char* p0 = (const char*)(AhG + cb + (size_t)i0*256);
    const char* p1 = (const char*)(AlG + cb + (size_t)i0*256);
    const char* p2 = (const char*)(BhG + cb + (size_t)j0*256);

    auto load_stage = [&](int st, int slot) {
        uint32_t base = sb + slot*TR_STAGE;
        #pragma unroll
        for (int i = 0; i < 6; i++) {
            int e = i*256 + t;
            int pl = e >> 9;
            int w_ = e & 511;
            int r = w_ >> 2, ch = (w_ & 3) * 16;
            const char* src = pl == 0 ? p0 : (pl == 1 ? p1 : p2);
            cp16s(base + (uint32_t)(pl*TPLANE + r*TSROW + ch),
                  src + (size_t)r*1024 + st*64 + ch);
        }
        cp_commit();
    };

    float acc[2][8][4];
    #pragma unroll
    for (int mt=0; mt<2; mt++)
        #pragma unroll
        for (int nt=0; nt<8; nt++)
            #pragma unroll
            for (int q=0; q<4; q++) acc[mt][nt][q]=0.f;

    int l16 = lane & 15;
    uint32_t coff = (uint32_t)((lane >> 4) * 16);

    load_stage(0, 0);
    load_stage(1, 1);

    #pragma unroll 1
    for (int st = 0; st < 16; st++) {
        if (st < 15) CP_WAIT(1); else CP_WAIT(0);
        __syncthreads();
        uint32_t base = sb + (st & 1)*TR_STAGE;
        #pragma unroll
        for (int kc = 0; kc < 2; kc++) {
            uint32_t kb = coff + kc*32;
            uint32_t Ah[2][4], Al[2][4];
            #pragma unroll
            for (int mt=0; mt<2; mt++) {
                uint32_t ar = (uint32_t)((m0 + mt*16 + l16) * TSROW) + kb;
                ldm_x4(Ah[mt], base + ar);
                ldm_x4(Al[mt], base + TPLANE + ar);
            }
            #pragma unroll
            for (int np=0; np<4; np++) {
                uint32_t br = (uint32_t)((n0 + np*16 + l16) * TSROW) + kb;
                uint32_t Bh[4];
                ldm_x4(Bh, base + 2*TPLANE + br);
                #pragma unroll
                for (int h=0; h<2; h++) {
                    uint32_t bh[2] = {Bh[h], Bh[2+h]};
                    int nt = np*2 + h;
                    #pragma unroll
                    for (int mt=0; mt<2; mt++)
                        MMA2T(acc[mt][nt], Ah[mt], Al[mt], bh);
                }
            }
        }
        __syncthreads();
        if (st + 2 < 16) load_stage(st + 2, st & 1);
    }

    uint32_t* O = Ot + (size_t)cz*(NN_/2);
    #pragma unroll
    for (int mt=0; mt<2; mt++) {
        int r = i0 + m0 + mt*16 + g;
        #pragma unroll
        for (int nt=0; nt<8; nt++) {
            int cl = j0 + n0 + nt*8 + 2*tg;
            O[(size_t)r*(N_/2) + cl/2]     = pack_h2(acc[mt][nt][0], acc[mt][nt][1]);
            O[(size_t)(r+8)*(N_/2) + cl/2] = pack_h2(acc[mt][nt][2], acc[mt][nt][3]);
        }
    }
}

// ---------------------------------------------------------------------------
// out_fused: 64-ij tile, 256 thr, 3 CTAs/SM.
// smem: OT16-staging-then-ON [0,34816) | WO [34816,69632) | lnwb 1KB
// ot is fp16 half2 c-major; gate fp16 half2 row-major; out fp32.
// ---------------------------------------------------------------------------
#define OF_WO   34816
#define OF_WS   69632
#define OF_SMEM 70656

__global__ __launch_bounds__(256, 3) void out_fused(
    const uint32_t* __restrict__ ot, const uint32_t* __restrict__ gate,
    const float* __restrict__ lnw, const float* __restrict__ lnb,
    const uint32_t* __restrict__ WoH,
    float* __restrict__ out)
{
    extern __shared__ char sm[];
    uint32_t sb = smem_u32(sm);
    int t = threadIdx.x, warp = t>>5, lane = t&31, g = lane>>2, tg = lane&3;
    int l16 = lane & 15;
    uint32_t coff = (uint32_t)((lane >> 4) * 16);
    int m0 = (warp & 1) * 32, n0 = (warp >> 1) * 32;
    size_t ij0 = (size_t)blockIdx.x * 64;

    // group1: OT16 tile: 128 c-rows x 128B (64 fp16), stride XROW
    #pragma unroll
    for (int i = 0; i < 4; i++) {
        int e = i*256 + t, c = e >> 3, ch = e & 7;
        cp16s(sb + (uint32_t)(c*XROW + ch*16),
              (const char*)(ot + (size_t)c*(NN_/2) + ij0/2) + ch*16);
    }
    cp_commit();
    // group2: WO hi plane (128 rows)
    #pragma unroll
    for (int i = 0; i < 8; i++) {
        int e = i*256 + t;
        int r = e >> 4, ch = e & 15;
        cp16s(sb + OF_WO + (uint32_t)(r*XROW + ch*16), WoH + (size_t)r*64 + ch*4);
    }
    cp_commit();

    if (t < 128) {
        ((float*)(sm + OF_WS))[t]       = lnw[t];
        ((float*)(sm + OF_WS))[128 + t] = lnb[t];
    }

    CP_WAIT(1); __syncthreads();   // OT16 ready

    // LN over c per ij -> ON planes (in place over OT16 region)
    {
        float* wv = (float*)(sm + OF_WS);
        int ij = t >> 2, q = t & 3;
        float y[32];
        float s1 = 0.f, s2 = 0.f;
        #pragma unroll
        for (int i = 0; i < 32; i++) {
            int c = q*32 + i;
            __half h = *(const __half*)(sm + c*XROW + ij*2);
            float v = __half2float(h);
            y[i] = v; s1 += v; s2 += v*v;
        }
        s1 += __shfl_xor_sync(~0u, s1, 1); s2 += __shfl_xor_sync(~0u, s2, 1);
        s1 += __shfl_xor_sync(~0u, s1, 2); s2 += __shfl_xor_sync(~0u, s2, 2);
        float mu  = s1 * (1.f/128.f);
        float var = s2 * (1.f/128.f) - mu*mu;
        float inv = rsqrtf(var + 1e-5f);
        __syncthreads();                    // all reads done before overwrite
        uint32_t* oh = (uint32_t*)(sm + ij*XROW);
        uint32_t* ol = (uint32_t*)(sm + XPL64 + ij*XROW);
        #pragma unroll
        for (int j = 0; j < 16; j++) {
            int c0 = q*32 + 2*j;
            float y0 = (y[2*j]   - mu) * inv * wv[c0]   + wv[128 + c0];
            float y1 = (y[2*j+1] - mu) * inv * wv[c0+1] + wv[128 + c0 + 1];
            uint2 p = pack_split(y0, y1);
            oh[q*16 + j] = p.x;
            ol[q*16 + j] = p.y;
        }
    }
    CP_WAIT(0); __syncthreads();   // ON written + WO ready

    float acc[2][4][4];
    #pragma unroll
    for (int mt=0; mt<2; mt++)
        #pragma unroll
        for (int nt=0; nt<4; nt++)
            #pragma unroll
            for (int q=0; q<4; q++) acc[mt][nt][q]=0.f;

    gemm64<XPL64>(sb, sb + OF_WO, acc, m0, n0, l16, coff);

    #pragma unroll
    for (int mt=0; mt<2; mt++) {
        size_t rl = ij0 + m0 + mt*16 + g;
        size_t rh = rl + 8;
        #pragma unroll
        for (int nt=0; nt<4; nt++) {
            int cl = n0 + nt*8 + 2*tg;
            __half2 glh = *(const __half2*)(gate + rl*64 + cl/2);
            __half2 ghh = *(const __half2*)(gate + rh*64 + cl/2);
            float2 gl = __half22float2(glh);
            float2 gh = __half22float2(ghh);
            *(float2*)(out + rl*C_ + cl) =
                make_float2(gl.x * acc[mt][nt][0], gl.y * acc[mt][nt][1]);
            *(float2*)(out + rh*C_ + cl) =
                make_float2(gh.x * acc[mt][nt][2], gh.y * acc[mt][nt][3]);
        }
    }
}

// ---------------------------------------------------------------------------
extern "C" void kernel_launch(void* const* d_in, const int* in_sizes, int n_in,
                              void* d_out, int out_size)
{
    const float* z      = (const float*)d_in[0];
    const float* mask   = (const float*)d_in[1];
    const float* ln_i_w = (const float*)d_in[2];
    const float* ln_i_b = (const float*)d_in[3];
    const float* ln_o_w = (const float*)d_in[4];
    const float* ln_o_b = (const float*)d_in[5];
    const float* w_pa   = (const float*)d_in[6];
    const float* w_pb   = (const float*)d_in[7];
    const float* w_ga   = (const float*)d_in[8];
    const float* w_gb   = (const float*)d_in[9];
    const float* w_g    = (const float*)d_in[10];
    const float* w_o    = (const float*)d_in[11];
    float* out = (float*)d_out;

    uint32_t *ath, *atl, *bth, *wh, *gt, *ot;
    cudaGetSymbolAddress((void**)&ath, g_ath);
    cudaGetSymbolAddress((void**)&atl, g_atl);
    cudaGetSymbolAddress((void**)&bth, g_bth);
    cudaGetSymbolAddress((void**)&wh,  g_wh);
    cudaGetSymbolAddress((void**)&gt,  g_gt);
    cudaGetSymbolAddress((void**)&ot,  g_ot);

    cudaFuncSetAttribute(proj_fused, cudaFuncAttributeMaxDynamicSharedMemorySize, PJ_SMEM);
    cudaFuncSetAttribute(out_fused,  cudaFuncAttributeMaxDynamicSharedMemorySize, OF_SMEM);
    cudaFuncSetAttribute(tri_lm,     cudaFuncAttributeMaxDynamicSharedMemorySize, TR_SMEM);

    // weight plane order: ga=0, pa=1, gb=2, pb=3, g=4, o=5
    split_w_lm<<<dim3(32, 6), 256>>>(w_ga, w_pa, w_gb, w_pb, w_g, w_o, wh);
    // LN(z) + 5 projections fused (64-row tiles, 2 CTAs/SM)
    proj_fused<<<NN_/64, 256, PJ_SMEM>>>(z, mask, ln_i_w, ln_i_b, wh,
                                         ath, atl, bth, gt);
    // triangle einsum -> ot fp16 c-major
    tri_lm<<<dim3(N_/128, N_/128, C_), 256, TR_SMEM>>>(ath, atl, bth, ot);
    // transpose+LN+GEMM+gate fused (64-ij tiles, 3 CTAs/SM)
    out_fused<<<NN_/64, 256, OF_SMEM>>>(ot, gt, ln_o_w, ln_o_b,
                                        wh + 5*C_*64, out);
}